// round 11
// baseline (speedup 1.0000x reference)
#include <cuda_runtime.h>
#include <cuda_bf16.h>
#include <math.h>
#include <stdint.h>

// ----------------------------------------------------------------------------
// Problem constants
// ----------------------------------------------------------------------------
#define B_   2
#define L_   2048
#define DIM_ 1024
#define H_   16
#define D_   64
#define BL_  (B_ * L_)         // 4096
#define BH_  (B_ * H_)         // 32

// Scratch (device globals — allocation-free per harness rules)
__device__ float g_qkv[BL_ * 3 * DIM_];                // [4096, 3072]
__device__ float g_q[BH_ * L_ * D_];                   // [B,H,L,D]
__device__ float g_k[BH_ * L_ * D_];
__device__ float g_v[BH_ * L_ * D_];

// bf16 hi/lo split operands
__device__ __nv_bfloat16 g_xh[BL_ * DIM_], g_xl[BL_ * DIM_];          // x
__device__ __nv_bfloat16 g_wqh[3 * DIM_ * DIM_], g_wql[3 * DIM_ * DIM_]; // w_qkv^T
__device__ __nv_bfloat16 g_wph[DIM_ * DIM_], g_wpl[DIM_ * DIM_];      // w_proj^T
__device__ __nv_bfloat16 g_oh[BL_ * DIM_], g_ol[BL_ * DIM_];          // attn out split

// ----------------------------------------------------------------------------
// helpers
// ----------------------------------------------------------------------------
__device__ __forceinline__ uint32_t f2tf32(float x) {
    uint32_t r;
    asm("cvt.rna.tf32.f32 %0, %1;" : "=r"(r) : "f"(x));
    return r;
}

__device__ __forceinline__ void mma_tf32(float* d, const uint32_t* a,
                                         uint32_t b0, uint32_t b1) {
    asm volatile(
        "mma.sync.aligned.m16n8k8.row.col.f32.tf32.tf32.f32 "
        "{%0,%1,%2,%3}, {%4,%5,%6,%7}, {%8,%9}, {%0,%1,%2,%3};\n"
        : "+f"(d[0]), "+f"(d[1]), "+f"(d[2]), "+f"(d[3])
        : "r"(a[0]), "r"(a[1]), "r"(a[2]), "r"(a[3]), "r"(b0), "r"(b1));
}

__device__ __forceinline__ void mma_bf16(float* d, const uint32_t* a,
                                         uint32_t b0, uint32_t b1) {
    asm volatile(
        "mma.sync.aligned.m16n8k16.row.col.f32.bf16.bf16.f32 "
        "{%0,%1,%2,%3}, {%4,%5,%6,%7}, {%8,%9}, {%0,%1,%2,%3};\n"
        : "+f"(d[0]), "+f"(d[1]), "+f"(d[2]), "+f"(d[3])
        : "r"(a[0]), "r"(a[1]), "r"(a[2]), "r"(a[3]), "r"(b0), "r"(b1));
}

__device__ __forceinline__ void ldsm_x4(uint32_t* r, uint32_t addr) {
    asm volatile("ldmatrix.sync.aligned.m8n8.x4.shared.b16 {%0,%1,%2,%3}, [%4];"
                 : "=r"(r[0]), "=r"(r[1]), "=r"(r[2]), "=r"(r[3]) : "r"(addr));
}

__device__ __forceinline__ void cpa16(uint32_t dst, const void* src) {
    asm volatile("cp.async.cg.shared.global [%0], [%1], 16;"
                 :: "r"(dst), "l"(src));
}
#define CP_COMMIT() asm volatile("cp.async.commit_group;" ::: "memory")
#define CP_WAIT0()  asm volatile("cp.async.wait_group 0;" ::: "memory")
#define CP_WAIT1()  asm volatile("cp.async.wait_group 1;" ::: "memory")

__device__ __forceinline__ void bfsplit(float v, __nv_bfloat16& h, __nv_bfloat16& l) {
    h = __float2bfloat16(v);
    l = __float2bfloat16(v - __bfloat162float(h));
}

// ----------------------------------------------------------------------------
// Elementwise hi/lo split: fp32 -> bf16 hi + bf16 lo
// ----------------------------------------------------------------------------
__global__ __launch_bounds__(256) void split_kernel(
    const float* __restrict__ s, __nv_bfloat16* __restrict__ hi,
    __nv_bfloat16* __restrict__ lo, int n)
{
    int i = (blockIdx.x * blockDim.x + threadIdx.x) * 4;
    if (i >= n) return;
    float4 v = *(const float4*)(s + i);
    __nv_bfloat16 h[4], l[4];
    bfsplit(v.x, h[0], l[0]);
    bfsplit(v.y, h[1], l[1]);
    bfsplit(v.z, h[2], l[2]);
    bfsplit(v.w, h[3], l[3]);
    uint2 ph, pl;
    ph.x = (uint32_t)__bfloat16_as_ushort(h[0]) | ((uint32_t)__bfloat16_as_ushort(h[1]) << 16);
    ph.y = (uint32_t)__bfloat16_as_ushort(h[2]) | ((uint32_t)__bfloat16_as_ushort(h[3]) << 16);
    pl.x = (uint32_t)__bfloat16_as_ushort(l[0]) | ((uint32_t)__bfloat16_as_ushort(l[1]) << 16);
    pl.y = (uint32_t)__bfloat16_as_ushort(l[2]) | ((uint32_t)__bfloat16_as_ushort(l[3]) << 16);
    *(uint2*)(hi + i) = ph;
    *(uint2*)(lo + i) = pl;
}

// ----------------------------------------------------------------------------
// Transpose + split: w[K][N] fp32 -> th/tl[N][K] bf16
// ----------------------------------------------------------------------------
__global__ __launch_bounds__(256) void tsplit_kernel(
    const float* __restrict__ w, __nv_bfloat16* __restrict__ th,
    __nv_bfloat16* __restrict__ tl, int K, int N)
{
    __shared__ float tile[32][33];
    const int t = threadIdx.x;
    const int k0 = blockIdx.y * 32;
    const int n0 = blockIdx.x * 32;
    const int rr = t >> 5;
    const int cc = t & 31;
#pragma unroll
    for (int i = 0; i < 4; i++)
        tile[rr + i * 8][cc] = w[(size_t)(k0 + rr + i * 8) * N + n0 + cc];
    __syncthreads();
#pragma unroll
    for (int i = 0; i < 4; i++) {
        int r = rr + i * 8;
        float v = tile[cc][r];
        __nv_bfloat16 h, l;
        bfsplit(v, h, l);
        th[(size_t)(n0 + r) * K + k0 + cc] = h;
        tl[(size_t)(n0 + r) * K + k0 + cc] = l;
    }
}

// ----------------------------------------------------------------------------
// bf16 3-term GEMM with ldmatrix fragment loads. C = A @ B^T (+bias).
// Ah/Al [M,K], Bh/Bl [N,K] bf16 K-major. Tiles 128x128x32, 8 warps,
// warp 64x32, double-buffered cp.async. Row stride 40 bf16 (80B) ->
// LDSM 16B segments i*80 mod 128 all distinct (conflict-free).
// ----------------------------------------------------------------------------
#define ROWW 20                    // row stride in 32-bit words (40 bf16)
#define ARRW (128 * ROWW)          // words per operand array
#define STW  (4 * ARRW)            // words per stage
#define GEMM_SMEM_BYTES (2 * STW * 4)   // 81920

__global__ __launch_bounds__(256, 2) void gemm_bf16s(
    const __nv_bfloat16* __restrict__ Ah, const __nv_bfloat16* __restrict__ Al,
    const __nv_bfloat16* __restrict__ Bh, const __nv_bfloat16* __restrict__ Bl,
    const float* __restrict__ bias, float* __restrict__ C,
    int M, int N, int K)
{
    extern __shared__ float sm[];
    const uint32_t smem_u32 = (uint32_t)__cvta_generic_to_shared(sm);

    const int tid  = threadIdx.x;
    const int lane = tid & 31;
    const int warp = tid >> 5;
    const int gid  = lane >> 2;
    const int tig  = lane & 3;
    const int warpm = warp & 1;
    const int warpn = warp >> 1;
    const int row0 = blockIdx.y * 128;
    const int col0 = blockIdx.x * 128;

    // staging roles: 4 arrays x 64 threads
    const int arr = tid >> 6;          // 0:Ah 1:Al 2:Bh 3:Bl
    const int g   = tid & 63;
    const int seg = g & 3;
    const int r0s = g >> 2;
    const __nv_bfloat16* sb =
        (arr == 0) ? Ah : (arr == 1) ? Al : (arr == 2) ? Bh : Bl;
    const int tile0 = (arr < 2) ? row0 : col0;
    const __nv_bfloat16* srcbase = sb + (size_t)(tile0 + r0s) * K + seg * 8;
    const uint32_t dstbase = smem_u32 + (uint32_t)(arr * ARRW + r0s * ROWW) * 4u
                             + (uint32_t)seg * 16u;

    // ldmatrix per-lane byte offsets (within stage)
    const int lm  = lane & 7;
    const int sel = lane >> 3;         // 0..3
    const uint32_t aoff = (uint32_t)(((warpm * 64 + (sel & 1) * 8 + lm) * ROWW
                                      + (sel >> 1) * 4) * 4);
    const uint32_t boff = (uint32_t)(((warpn * 32 + (sel >> 1) * 8 + lm) * ROWW
                                      + (sel & 1) * 4) * 4);

    float acc[4][4][4];
#pragma unroll
    for (int mt = 0; mt < 4; mt++)
#pragma unroll
        for (int nt = 0; nt < 4; nt++)
#pragma unroll
            for (int j = 0; j < 4; j++) acc[mt][nt][j] = 0.f;

    const int nch = K >> 5;

    // prologue: stage chunk 0
#pragma unroll
    for (int it = 0; it < 8; it++)
        cpa16(dstbase + (uint32_t)(it * 16 * ROWW) * 4u,
              srcbase + (size_t)(it * 16) * K);
    CP_COMMIT();

    for (int ch = 0; ch < nch; ch++) {
        if (ch + 1 < nch) {
            uint32_t db = dstbase + (uint32_t)(((ch + 1) & 1) * STW) * 4u;
            const __nv_bfloat16* srck = srcbase + (ch + 1) * 32;
#pragma unroll
            for (int it = 0; it < 8; it++)
                cpa16(db + (uint32_t)(it * 16 * ROWW) * 4u,
                      srck + (size_t)(it * 16) * K);
            CP_COMMIT();
            CP_WAIT1();
        } else {
            CP_WAIT0();
        }
        __syncthreads();

        const uint32_t sbase = smem_u32 + (uint32_t)((ch & 1) * STW) * 4u;

#pragma unroll
        for (int ks = 0; ks < 2; ks++) {
            const uint32_t kb = (uint32_t)(ks * 32);   // 8 words
            // A fragments: 8x ldmatrix.x4
            uint32_t ah[4][4], al[4][4];
#pragma unroll
            for (int mt = 0; mt < 4; mt++) {
                uint32_t ao = sbase + aoff + (uint32_t)(mt * 16 * ROWW) * 4u + kb;
                ldsm_x4(ah[mt], ao);
                ldsm_x4(al[mt], ao + (uint32_t)(ARRW * 4));
            }
            // B fragments per nt-pair, then MMAs (keeps B live range small)
#pragma unroll
            for (int p = 0; p < 2; p++) {
                uint32_t bo = sbase + boff + (uint32_t)((2 * ARRW + p * 16 * ROWW) * 4) + kb;
                uint32_t bhp[4], blp[4];
                ldsm_x4(bhp, bo);
                ldsm_x4(blp, bo + (uint32_t)(ARRW * 4));
#pragma unroll
                for (int q = 0; q < 2; q++) {
                    const int nt = p * 2 + q;
                    uint32_t bh0 = bhp[q * 2], bh1 = bhp[q * 2 + 1];
                    uint32_t bl0 = blp[q * 2], bl1 = blp[q * 2 + 1];
#pragma unroll
                    for (int mt = 0; mt < 4; mt++) {
                        mma_bf16(acc[mt][nt], al[mt], bh0, bh1);   // Al*Bh
                        mma_bf16(acc[mt][nt], ah[mt], bl0, bl1);   // Ah*Bl
                        mma_bf16(acc[mt][nt], ah[mt], bh0, bh1);   // Ah*Bh
                    }
                }
            }
        }
        __syncthreads();
    }

    // epilogue
#pragma unroll
    for (int mt = 0; mt < 4; mt++) {
        int gr = row0 + warpm * 64 + mt * 16 + gid;
#pragma unroll
        for (int nt = 0; nt < 4; nt++) {
            int gc = col0 + warpn * 32 + nt * 8 + 2 * tig;
            float b0 = 0.f, b1 = 0.f;
            if (bias) { b0 = bias[gc]; b1 = bias[gc + 1]; }
            float2 c01 = {acc[mt][nt][0] + b0, acc[mt][nt][1] + b1};
            float2 c23 = {acc[mt][nt][2] + b0, acc[mt][nt][3] + b1};
            *(float2*)(C + (size_t)gr * N + gc) = c01;
            *(float2*)(C + (size_t)(gr + 8) * N + gc) = c23;
        }
    }
}

// ----------------------------------------------------------------------------
// RMSNorm (over D=64) + RoPE; split qkv into q/k/v in [B,H,L,D].
// ----------------------------------------------------------------------------
__global__ __launch_bounds__(256) void rmsrope_kernel(
    const float* __restrict__ qkv, const float* __restrict__ pe,
    const float* __restrict__ qscale, const float* __restrict__ kscale,
    float* __restrict__ q, float* __restrict__ k, float* __restrict__ v)
{
    const int warp = (blockIdx.x * blockDim.x + threadIdx.x) >> 5;
    const int lane = threadIdx.x & 31;
    const int b = warp >> 15;
    const int rem = warp & 32767;
    const int h = rem >> 11;
    const int l = rem & 2047;

    const float* base = qkv + ((size_t)(b * L_ + l)) * (3 * DIM_) + h * D_;
    float2 q2 = *(const float2*)(base + lane * 2);
    float2 k2 = *(const float2*)(base + DIM_ + lane * 2);
    float2 v2 = *(const float2*)(base + 2 * DIM_ + lane * 2);

    float sq = q2.x * q2.x + q2.y * q2.y;
    float sk = k2.x * k2.x + k2.y * k2.y;
#pragma unroll
    for (int o = 16; o > 0; o >>= 1) {
        sq += __shfl_xor_sync(0xffffffffu, sq, o);
        sk += __shfl_xor_sync(0xffffffffu, sk, o);
    }
    const float qinv = rsqrtf(sq * (1.f / 64.f) + 1e-6f);
    const float kinv = rsqrtf(sk * (1.f / 64.f) + 1e-6f);

    float2 qsc = *(const float2*)(qscale + lane * 2);
    float2 ksc = *(const float2*)(kscale + lane * 2);
    float t0 = q2.x * qinv * qsc.x;
    float t1 = q2.y * qinv * qsc.y;
    float u0 = k2.x * kinv * ksc.x;
    float u1 = k2.y * kinv * ksc.y;

    float4 p = *(const float4*)(pe + (((size_t)(b * L_ + l)) * 32 + lane) * 4);
    float2 qo, ko;
    qo.x = p.x * t0 + p.y * t1;
    qo.y = p.z * t0 + p.w * t1;
    ko.x = p.x * u0 + p.y * u1;
    ko.y = p.z * u0 + p.w * u1;

    const size_t orow = ((size_t)((b * H_ + h) * L_ + l)) * D_;
    *(float2*)(q + orow + lane * 2) = qo;
    *(float2*)(k + orow + lane * 2) = ko;
    *(float2*)(v + orow + lane * 2) = v2;
}

// ----------------------------------------------------------------------------
// Flash attention (tf32 mma). 8 warps / 128 queries per block: halves K/V
// staging per query, 24 warps/SM. Epilogue writes bf16 hi/lo split directly.
// ----------------------------------------------------------------------------
#define PAD 68
#define SK_OFF   0
#define SV_OFF   (64 * PAD)
#define SP_OFF   (2 * 64 * PAD)
#define ATTN_SMEM_FLOATS (2 * 64 * PAD + 8 * 16 * PAD)
#define ATTN_SMEM_BYTES  (ATTN_SMEM_FLOATS * 4)     // 69632

__global__ __launch_bounds__(256) void attn_mma(
    const float* __restrict__ q, const float* __restrict__ k,
    const float* __restrict__ v,
    __nv_bfloat16* __restrict__ oh, __nv_bfloat16* __restrict__ ol)
{
    extern __shared__ float sm[];
    float* sK = sm + SK_OFF;
    float* sV = sm + SV_OFF;
    float* sP = sm + SP_OFF;

    const int tid  = threadIdx.x;
    const int lane = tid & 31;
    const int warp = tid >> 5;          // 0..7
    const int gid  = lane >> 2;
    const int tig  = lane & 3;
    const int bh = blockIdx.y;
    const int q0 = blockIdx.x * 128;
    const size_t bhoff = (size_t)bh * L_ * D_;
    const float* Q = q + bhoff;
    const float* K = k + bhoff;
    const float* V = v + bhoff;

    const float QSCALE = 0.125f * 1.4426950408889634f;

    const int r0 = q0 + warp * 16 + gid;
    uint32_t qf[8][4];
#pragma unroll
    for (int kk = 0; kk < 8; kk++) {
        qf[kk][0] = f2tf32(Q[(size_t)r0 * D_ + kk * 8 + tig] * QSCALE);
        qf[kk][1] = f2tf32(Q[(size_t)(r0 + 8) * D_ + kk * 8 + tig] * QSCALE);
        qf[kk][2] = f2tf32(Q[(size_t)r0 * D_ + kk * 8 + tig + 4] * QSCALE);
        qf[kk][3] = f2tf32(Q[(size_t)(r0 + 8) * D_ + kk * 8 + tig + 4] * QSCALE);
    }

    float of[8][4];
#pragma unroll
    for (int nt = 0; nt < 8; nt++)
#pragma unroll
        for (int j = 0; j < 4; j++) of[nt][j] = 0.f;

    float m0 = -INFINITY, m1 = -INFINITY;
    float l0 = 0.f, l1 = 0.f;

    uint32_t* sPw = (uint32_t*)(sP + warp * 16 * PAD);

    for (int c0 = 0; c0 < L_; c0 += 64) {
        // ---- stage K,V tile (64 rows x 16 c4-groups = 1024 items, 256 thr) ----
#pragma unroll
        for (int it = 0; it < 4; it++) {
            int idx = tid + it * 256;
            int r = idx >> 4;
            int c4 = idx & 15;
            float4 a = *(const float4*)(K + (size_t)(c0 + r) * D_ + c4 * 4);
            uint4 ua = {f2tf32(a.x), f2tf32(a.y), f2tf32(a.z), f2tf32(a.w)};
            *(uint4*)(&sK[r * PAD + c4 * 4]) = ua;
            float4 bv = *(const float4*)(V + (size_t)(c0 + r) * D_ + c4 * 4);
            uint4 ub = {f2tf32(bv.x), f2tf32(bv.y), f2tf32(bv.z), f2tf32(bv.w)};
            *(uint4*)(&sV[r * PAD + c4 * 4]) = ub;
        }
        __syncthreads();

        // ---- S = Q K^T ----
        float sf[8][4];
#pragma unroll
        for (int nt = 0; nt < 8; nt++)
#pragma unroll
            for (int j = 0; j < 4; j++) sf[nt][j] = 0.f;

        const uint32_t* sKu = (const uint32_t*)sK;
#pragma unroll
        for (int kk = 0; kk < 8; kk++) {
#pragma unroll
            for (int nt = 0; nt < 8; nt++) {
                uint32_t b0 = sKu[(nt * 8 + gid) * PAD + kk * 8 + tig];
                uint32_t b1 = sKu[(nt * 8 + gid) * PAD + kk * 8 + tig + 4];
                mma_tf32(sf[nt], qf[kk], b0, b1);
            }
        }

        // ---- online softmax in registers ----
        float mn0 = m0, mn1 = m1;
#pragma unroll
        for (int nt = 0; nt < 8; nt++) {
            mn0 = fmaxf(mn0, fmaxf(sf[nt][0], sf[nt][1]));
            mn1 = fmaxf(mn1, fmaxf(sf[nt][2], sf[nt][3]));
        }
        mn0 = fmaxf(mn0, __shfl_xor_sync(0xffffffffu, mn0, 1));
        mn0 = fmaxf(mn0, __shfl_xor_sync(0xffffffffu, mn0, 2));
        mn1 = fmaxf(mn1, __shfl_xor_sync(0xffffffffu, mn1, 1));
        mn1 = fmaxf(mn1, __shfl_xor_sync(0xffffffffu, mn1, 2));
        float a0 = exp2f(m0 - mn0);
        float a1 = exp2f(m1 - mn1);
        m0 = mn0; m1 = mn1;
        l0 *= a0; l1 *= a1;

#pragma unroll
        for (int nt = 0; nt < 8; nt++) {
            float p00 = exp2f(sf[nt][0] - m0);
            float p01 = exp2f(sf[nt][1] - m0);
            float p10 = exp2f(sf[nt][2] - m1);
            float p11 = exp2f(sf[nt][3] - m1);
            l0 += p00 + p01;
            l1 += p10 + p11;
            uint2 u0 = {f2tf32(p00), f2tf32(p01)};
            uint2 u1 = {f2tf32(p10), f2tf32(p11)};
            *(uint2*)(&sPw[gid * PAD + nt * 8 + 2 * tig]) = u0;
            *(uint2*)(&sPw[(gid + 8) * PAD + nt * 8 + 2 * tig]) = u1;
            of[nt][0] *= a0; of[nt][1] *= a0;
            of[nt][2] *= a1; of[nt][3] *= a1;
        }
        __syncwarp();

        // ---- O += P @ V ----
        const uint32_t* sVu = (const uint32_t*)sV;
#pragma unroll
        for (int kk = 0; kk < 8; kk++) {
            uint32_t af[4];
            af[0] = sPw[gid * PAD + kk * 8 + tig];
            af[1] = sPw[(gid + 8) * PAD + kk * 8 + tig];
            af[2] = sPw[gid * PAD + kk * 8 + tig + 4];
            af[3] = sPw[(gid + 8) * PAD + kk * 8 + tig + 4];
#pragma unroll
            for (int nt = 0; nt < 8; nt++) {
                uint32_t b0 = sVu[(kk * 8 + tig) * PAD + nt * 8 + gid];
                uint32_t b1 = sVu[(kk * 8 + tig + 4) * PAD + nt * 8 + gid];
                mma_tf32(of[nt], af, b0, b1);
            }
        }
        __syncthreads();
    }

    // ---- epilogue: normalize + write bf16 hi/lo split in [B,L,H,D] ----
    l0 += __shfl_xor_sync(0xffffffffu, l0, 1);
    l0 += __shfl_xor_sync(0xffffffffu, l0, 2);
    l1 += __shfl_xor_sync(0xffffffffu, l1, 1);
    l1 += __shfl_xor_sync(0xffffffffu, l1, 2);
    const float inv0 = 1.f / l0;
    const float inv1 = 1.f / l1;

    const int b = bh >> 4;
    const int h = bh & 15;
    const size_t row0 = (((size_t)(b * L_ + r0)) * H_ + h) * D_;
    const size_t row1 = (((size_t)(b * L_ + r0 + 8)) * H_ + h) * D_;
#pragma unroll
    for (int nt = 0; nt < 8; nt++) {
        float v00 = of[nt][0] * inv0, v01 = of[nt][1] * inv0;
        float v10 = of[nt][2] * inv1, v11 = of[nt][3] * inv1;
        __nv_bfloat16 h0, l0b, h1, l1b, h2, l2b, h3, l3b;
        bfsplit(v00, h0, l0b); bfsplit(v01, h1, l1b);
        bfsplit(v10, h2, l2b); bfsplit(v11, h3, l3b);
        uint32_t ph0 = (uint32_t)__bfloat16_as_ushort(h0) | ((uint32_t)__bfloat16_as_ushort(h1) << 16);
        uint32_t pl0 = (uint32_t)__bfloat16_as_ushort(l0b) | ((uint32_t)__bfloat16_as_ushort(l1b) << 16);
        uint32_t ph1 = (uint32_t)__bfloat16_as_ushort(h2) | ((uint32_t)__bfloat16_as_ushort(h3) << 16);
        uint32_t pl1 = (uint32_t)__bfloat16_as_ushort(l2b) | ((uint32_t)__bfloat16_as_ushort(l3b) << 16);
        *(uint32_t*)(oh + row0 + nt * 8 + 2 * tig) = ph0;
        *(uint32_t*)(ol + row0 + nt * 8 + 2 * tig) = pl0;
        *(uint32_t*)(oh + row1 + nt * 8 + 2 * tig) = ph1;
        *(uint32_t*)(ol + row1 + nt * 8 + 2 * tig) = pl1;
    }
}

// ----------------------------------------------------------------------------
// Launch
// ----------------------------------------------------------------------------
extern "C" void kernel_launch(void* const* d_in, const int* in_sizes, int n_in,
                              void* d_out, int out_size)
{
    const float* x      = (const float*)d_in[0];
    const float* pe     = (const float*)d_in[1];
    const float* w_qkv  = (const float*)d_in[2];
    const float* qscale = (const float*)d_in[3];
    const float* kscale = (const float*)d_in[4];
    const float* w_proj = (const float*)d_in[5];
    const float* b_proj = (const float*)d_in[6];
    float* out = (float*)d_out;

    float *p_qkv, *p_q, *p_k, *p_v;
    cudaGetSymbolAddress((void**)&p_qkv, g_qkv);
    cudaGetSymbolAddress((void**)&p_q, g_q);
    cudaGetSymbolAddress((void**)&p_k, g_k);
    cudaGetSymbolAddress((void**)&p_v, g_v);

    __nv_bfloat16 *p_xh, *p_xl, *p_wqh, *p_wql, *p_wph, *p_wpl, *p_oh, *p_ol;
    cudaGetSymbolAddress((void**)&p_xh, g_xh);
    cudaGetSymbolAddress((void**)&p_xl, g_xl);
    cudaGetSymbolAddress((void**)&p_wqh, g_wqh);
    cudaGetSymbolAddress((void**)&p_wql, g_wql);
    cudaGetSymbolAddress((void**)&p_wph, g_wph);
    cudaGetSymbolAddress((void**)&p_wpl, g_wpl);
    cudaGetSymbolAddress((void**)&p_oh, g_oh);
    cudaGetSymbolAddress((void**)&p_ol, g_ol);

    cudaFuncSetAttribute(attn_mma, cudaFuncAttributeMaxDynamicSharedMemorySize,
                         ATTN_SMEM_BYTES);
    cudaFuncSetAttribute(gemm_bf16s, cudaFuncAttributeMaxDynamicSharedMemorySize,
                         GEMM_SMEM_BYTES);

    // 0a. split x -> bf16 hi/lo
    split_kernel<<<BL_ * DIM_ / 1024, 256>>>(x, p_xh, p_xl, BL_ * DIM_);
    // 0b. transpose+split weights
    {
        dim3 gq(3 * DIM_ / 32, DIM_ / 32);
        tsplit_kernel<<<gq, 256>>>(w_qkv, p_wqh, p_wql, DIM_, 3 * DIM_);
        dim3 gp(DIM_ / 32, DIM_ / 32);
        tsplit_kernel<<<gp, 256>>>(w_proj, p_wph, p_wpl, DIM_, DIM_);
    }
    // 1. QKV GEMM (bf16 3-term, ldmatrix): [4096,1024] @ [1024,3072]
    {
        dim3 grid(3 * DIM_ / 128, BL_ / 128);
        gemm_bf16s<<<grid, 256, GEMM_SMEM_BYTES>>>(p_xh, p_xl, p_wqh, p_wql,
                                                   nullptr, p_qkv,
                                                   BL_, 3 * DIM_, DIM_);
    }
    // 2. RMSNorm + RoPE + split
    {
        int warps = B_ * H_ * L_;
        rmsrope_kernel<<<warps * 32 / 256, 256>>>(p_qkv, pe, qscale, kscale,
                                                  p_q, p_k, p_v);
    }
    // 3. Attention (tf32 mma, 128 queries/block, fused split epilogue)
    {
        dim3 grid(L_ / 128, BH_);
        attn_mma<<<grid, 256, ATTN_SMEM_BYTES>>>(p_q, p_k, p_v, p_oh, p_ol);
    }
    // 4. Output projection (bf16 3-term) + bias
    {
        dim3 grid(DIM_ / 128, BL_ / 128);
        gemm_bf16s<<<grid, 256, GEMM_SMEM_BYTES>>>(p_oh, p_ol, p_wph, p_wpl,
                                                   b_proj, out,
                                                   BL_, DIM_, DIM_);
    }
}

// round 12
// speedup vs baseline: 1.1274x; 1.1274x over previous
#include <cuda_runtime.h>
#include <cuda_bf16.h>
#include <math.h>
#include <stdint.h>

// ----------------------------------------------------------------------------
// Problem constants
// ----------------------------------------------------------------------------
#define B_   2
#define L_   2048
#define DIM_ 1024
#define H_   16
#define D_   64
#define BL_  (B_ * L_)         // 4096
#define BH_  (B_ * H_)         // 32

// Scratch (device globals — allocation-free per harness rules)
__device__ float g_qkv[BL_ * 3 * DIM_];                // [4096, 3072]
__device__ float g_q[BH_ * L_ * D_];                   // [B,H,L,D]
__device__ float g_k[BH_ * L_ * D_];
__device__ float g_v[BH_ * L_ * D_];

// bf16 hi/lo split operands
__device__ __nv_bfloat16 g_xh[BL_ * DIM_], g_xl[BL_ * DIM_];          // x
__device__ __nv_bfloat16 g_wqh[3 * DIM_ * DIM_], g_wql[3 * DIM_ * DIM_]; // w_qkv^T
__device__ __nv_bfloat16 g_wph[DIM_ * DIM_], g_wpl[DIM_ * DIM_];      // w_proj^T
__device__ __nv_bfloat16 g_oh[BL_ * DIM_], g_ol[BL_ * DIM_];          // attn out split

// ----------------------------------------------------------------------------
// helpers
// ----------------------------------------------------------------------------
__device__ __forceinline__ uint32_t f2tf32(float x) {
    uint32_t r;
    asm("cvt.rna.tf32.f32 %0, %1;" : "=r"(r) : "f"(x));
    return r;
}

__device__ __forceinline__ void mma_tf32(float* d, const uint32_t* a,
                                         uint32_t b0, uint32_t b1) {
    asm volatile(
        "mma.sync.aligned.m16n8k8.row.col.f32.tf32.tf32.f32 "
        "{%0,%1,%2,%3}, {%4,%5,%6,%7}, {%8,%9}, {%0,%1,%2,%3};\n"
        : "+f"(d[0]), "+f"(d[1]), "+f"(d[2]), "+f"(d[3])
        : "r"(a[0]), "r"(a[1]), "r"(a[2]), "r"(a[3]), "r"(b0), "r"(b1));
}

__device__ __forceinline__ void mma_bf16(float* d, const uint32_t* a,
                                         uint32_t b0, uint32_t b1) {
    asm volatile(
        "mma.sync.aligned.m16n8k16.row.col.f32.bf16.bf16.f32 "
        "{%0,%1,%2,%3}, {%4,%5,%6,%7}, {%8,%9}, {%0,%1,%2,%3};\n"
        : "+f"(d[0]), "+f"(d[1]), "+f"(d[2]), "+f"(d[3])
        : "r"(a[0]), "r"(a[1]), "r"(a[2]), "r"(a[3]), "r"(b0), "r"(b1));
}

__device__ __forceinline__ void ldsm_x4(uint32_t* r, uint32_t addr) {
    asm volatile("ldmatrix.sync.aligned.m8n8.x4.shared.b16 {%0,%1,%2,%3}, [%4];"
                 : "=r"(r[0]), "=r"(r[1]), "=r"(r[2]), "=r"(r[3]) : "r"(addr));
}

__device__ __forceinline__ void cpa16(uint32_t dst, const void* src) {
    asm volatile("cp.async.cg.shared.global [%0], [%1], 16;"
                 :: "r"(dst), "l"(src));
}
#define CP_COMMIT() asm volatile("cp.async.commit_group;" ::: "memory")
#define CP_WAIT0()  asm volatile("cp.async.wait_group 0;" ::: "memory")
#define CP_WAIT1()  asm volatile("cp.async.wait_group 1;" ::: "memory")

__device__ __forceinline__ void bfsplit(float v, __nv_bfloat16& h, __nv_bfloat16& l) {
    h = __float2bfloat16(v);
    l = __float2bfloat16(v - __bfloat162float(h));
}

// ----------------------------------------------------------------------------
// Elementwise hi/lo split: fp32 -> bf16 hi + bf16 lo
// ----------------------------------------------------------------------------
__global__ __launch_bounds__(256) void split_kernel(
    const float* __restrict__ s, __nv_bfloat16* __restrict__ hi,
    __nv_bfloat16* __restrict__ lo, int n)
{
    int i = (blockIdx.x * blockDim.x + threadIdx.x) * 4;
    if (i >= n) return;
    float4 v = *(const float4*)(s + i);
    __nv_bfloat16 h[4], l[4];
    bfsplit(v.x, h[0], l[0]);
    bfsplit(v.y, h[1], l[1]);
    bfsplit(v.z, h[2], l[2]);
    bfsplit(v.w, h[3], l[3]);
    uint2 ph, pl;
    ph.x = (uint32_t)__bfloat16_as_ushort(h[0]) | ((uint32_t)__bfloat16_as_ushort(h[1]) << 16);
    ph.y = (uint32_t)__bfloat16_as_ushort(h[2]) | ((uint32_t)__bfloat16_as_ushort(h[3]) << 16);
    pl.x = (uint32_t)__bfloat16_as_ushort(l[0]) | ((uint32_t)__bfloat16_as_ushort(l[1]) << 16);
    pl.y = (uint32_t)__bfloat16_as_ushort(l[2]) | ((uint32_t)__bfloat16_as_ushort(l[3]) << 16);
    *(uint2*)(hi + i) = ph;
    *(uint2*)(lo + i) = pl;
}

// ----------------------------------------------------------------------------
// Transpose + split: w[K][N] fp32 -> th/tl[N][K] bf16
// ----------------------------------------------------------------------------
__global__ __launch_bounds__(256) void tsplit_kernel(
    const float* __restrict__ w, __nv_bfloat16* __restrict__ th,
    __nv_bfloat16* __restrict__ tl, int K, int N)
{
    __shared__ float tile[32][33];
    const int t = threadIdx.x;
    const int k0 = blockIdx.y * 32;
    const int n0 = blockIdx.x * 32;
    const int rr = t >> 5;
    const int cc = t & 31;
#pragma unroll
    for (int i = 0; i < 4; i++)
        tile[rr + i * 8][cc] = w[(size_t)(k0 + rr + i * 8) * N + n0 + cc];
    __syncthreads();
#pragma unroll
    for (int i = 0; i < 4; i++) {
        int r = rr + i * 8;
        float v = tile[cc][r];
        __nv_bfloat16 h, l;
        bfsplit(v, h, l);
        th[(size_t)(n0 + r) * K + k0 + cc] = h;
        tl[(size_t)(n0 + r) * K + k0 + cc] = l;
    }
}

// ----------------------------------------------------------------------------
// bf16 3-term GEMM with ldmatrix fragment loads. C = A @ B^T (+bias).
// Unchanged from round 11 (proven: QKV 219us, tensor 58%).
// ----------------------------------------------------------------------------
#define ROWW 20                    // row stride in 32-bit words (40 bf16)
#define ARRW (128 * ROWW)
#define STW  (4 * ARRW)
#define GEMM_SMEM_BYTES (2 * STW * 4)   // 81920

__global__ __launch_bounds__(256, 2) void gemm_bf16s(
    const __nv_bfloat16* __restrict__ Ah, const __nv_bfloat16* __restrict__ Al,
    const __nv_bfloat16* __restrict__ Bh, const __nv_bfloat16* __restrict__ Bl,
    const float* __restrict__ bias, float* __restrict__ C,
    int M, int N, int K)
{
    extern __shared__ float sm[];
    const uint32_t smem_u32 = (uint32_t)__cvta_generic_to_shared(sm);

    const int tid  = threadIdx.x;
    const int lane = tid & 31;
    const int warp = tid >> 5;
    const int gid  = lane >> 2;
    const int tig  = lane & 3;
    const int warpm = warp & 1;
    const int warpn = warp >> 1;
    const int row0 = blockIdx.y * 128;
    const int col0 = blockIdx.x * 128;

    const int arr = tid >> 6;
    const int g   = tid & 63;
    const int seg = g & 3;
    const int r0s = g >> 2;
    const __nv_bfloat16* sb =
        (arr == 0) ? Ah : (arr == 1) ? Al : (arr == 2) ? Bh : Bl;
    const int tile0 = (arr < 2) ? row0 : col0;
    const __nv_bfloat16* srcbase = sb + (size_t)(tile0 + r0s) * K + seg * 8;
    const uint32_t dstbase = smem_u32 + (uint32_t)(arr * ARRW + r0s * ROWW) * 4u
                             + (uint32_t)seg * 16u;

    const int lm  = lane & 7;
    const int sel = lane >> 3;
    const uint32_t aoff = (uint32_t)(((warpm * 64 + (sel & 1) * 8 + lm) * ROWW
                                      + (sel >> 1) * 4) * 4);
    const uint32_t boff = (uint32_t)(((warpn * 32 + (sel >> 1) * 8 + lm) * ROWW
                                      + (sel & 1) * 4) * 4);

    float acc[4][4][4];
#pragma unroll
    for (int mt = 0; mt < 4; mt++)
#pragma unroll
        for (int nt = 0; nt < 4; nt++)
#pragma unroll
            for (int j = 0; j < 4; j++) acc[mt][nt][j] = 0.f;

    const int nch = K >> 5;

#pragma unroll
    for (int it = 0; it < 8; it++)
        cpa16(dstbase + (uint32_t)(it * 16 * ROWW) * 4u,
              srcbase + (size_t)(it * 16) * K);
    CP_COMMIT();

    for (int ch = 0; ch < nch; ch++) {
        if (ch + 1 < nch) {
            uint32_t db = dstbase + (uint32_t)(((ch + 1) & 1) * STW) * 4u;
            const __nv_bfloat16* srck = srcbase + (ch + 1) * 32;
#pragma unroll
            for (int it = 0; it < 8; it++)
                cpa16(db + (uint32_t)(it * 16 * ROWW) * 4u,
                      srck + (size_t)(it * 16) * K);
            CP_COMMIT();
            CP_WAIT1();
        } else {
            CP_WAIT0();
        }
        __syncthreads();

        const uint32_t sbase = smem_u32 + (uint32_t)((ch & 1) * STW) * 4u;

#pragma unroll
        for (int ks = 0; ks < 2; ks++) {
            const uint32_t kb = (uint32_t)(ks * 32);
            uint32_t ah[4][4], al[4][4];
#pragma unroll
            for (int mt = 0; mt < 4; mt++) {
                uint32_t ao = sbase + aoff + (uint32_t)(mt * 16 * ROWW) * 4u + kb;
                ldsm_x4(ah[mt], ao);
                ldsm_x4(al[mt], ao + (uint32_t)(ARRW * 4));
            }
#pragma unroll
            for (int p = 0; p < 2; p++) {
                uint32_t bo = sbase + boff + (uint32_t)((2 * ARRW + p * 16 * ROWW) * 4) + kb;
                uint32_t bhp[4], blp[4];
                ldsm_x4(bhp, bo);
                ldsm_x4(blp, bo + (uint32_t)(ARRW * 4));
#pragma unroll
                for (int q = 0; q < 2; q++) {
                    const int nt = p * 2 + q;
                    uint32_t bh0 = bhp[q * 2], bh1 = bhp[q * 2 + 1];
                    uint32_t bl0 = blp[q * 2], bl1 = blp[q * 2 + 1];
#pragma unroll
                    for (int mt = 0; mt < 4; mt++) {
                        mma_bf16(acc[mt][nt], al[mt], bh0, bh1);
                        mma_bf16(acc[mt][nt], ah[mt], bl0, bl1);
                        mma_bf16(acc[mt][nt], ah[mt], bh0, bh1);
                    }
                }
            }
        }
        __syncthreads();
    }

#pragma unroll
    for (int mt = 0; mt < 4; mt++) {
        int gr = row0 + warpm * 64 + mt * 16 + gid;
#pragma unroll
        for (int nt = 0; nt < 4; nt++) {
            int gc = col0 + warpn * 32 + nt * 8 + 2 * tig;
            float b0 = 0.f, b1 = 0.f;
            if (bias) { b0 = bias[gc]; b1 = bias[gc + 1]; }
            float2 c01 = {acc[mt][nt][0] + b0, acc[mt][nt][1] + b1};
            float2 c23 = {acc[mt][nt][2] + b0, acc[mt][nt][3] + b1};
            *(float2*)(C + (size_t)gr * N + gc) = c01;
            *(float2*)(C + (size_t)(gr + 8) * N + gc) = c23;
        }
    }
}

// ----------------------------------------------------------------------------
// RMSNorm (over D=64) + RoPE; split qkv into q/k/v in [B,H,L,D].
// ----------------------------------------------------------------------------
__global__ __launch_bounds__(256) void rmsrope_kernel(
    const float* __restrict__ qkv, const float* __restrict__ pe,
    const float* __restrict__ qscale, const float* __restrict__ kscale,
    float* __restrict__ q, float* __restrict__ k, float* __restrict__ v)
{
    const int warp = (blockIdx.x * blockDim.x + threadIdx.x) >> 5;
    const int lane = threadIdx.x & 31;
    const int b = warp >> 15;
    const int rem = warp & 32767;
    const int h = rem >> 11;
    const int l = rem & 2047;

    const float* base = qkv + ((size_t)(b * L_ + l)) * (3 * DIM_) + h * D_;
    float2 q2 = *(const float2*)(base + lane * 2);
    float2 k2 = *(const float2*)(base + DIM_ + lane * 2);
    float2 v2 = *(const float2*)(base + 2 * DIM_ + lane * 2);

    float sq = q2.x * q2.x + q2.y * q2.y;
    float sk = k2.x * k2.x + k2.y * k2.y;
#pragma unroll
    for (int o = 16; o > 0; o >>= 1) {
        sq += __shfl_xor_sync(0xffffffffu, sq, o);
        sk += __shfl_xor_sync(0xffffffffu, sk, o);
    }
    const float qinv = rsqrtf(sq * (1.f / 64.f) + 1e-6f);
    const float kinv = rsqrtf(sk * (1.f / 64.f) + 1e-6f);

    float2 qsc = *(const float2*)(qscale + lane * 2);
    float2 ksc = *(const float2*)(kscale + lane * 2);
    float t0 = q2.x * qinv * qsc.x;
    float t1 = q2.y * qinv * qsc.y;
    float u0 = k2.x * kinv * ksc.x;
    float u1 = k2.y * kinv * ksc.y;

    float4 p = *(const float4*)(pe + (((size_t)(b * L_ + l)) * 32 + lane) * 4);
    float2 qo, ko;
    qo.x = p.x * t0 + p.y * t1;
    qo.y = p.z * t0 + p.w * t1;
    ko.x = p.x * u0 + p.y * u1;
    ko.y = p.z * u0 + p.w * u1;

    const size_t orow = ((size_t)((b * H_ + h) * L_ + l)) * D_;
    *(float2*)(q + orow + lane * 2) = qo;
    *(float2*)(k + orow + lane * 2) = ko;
    *(float2*)(v + orow + lane * 2) = v2;
}

// ----------------------------------------------------------------------------
// Flash attention (tf32 mma). REVERTED to the proven 4-warp/128-thread,
// 64-queries-per-block shape (round-10 perf), but with the fused bf16 hi/lo
// split epilogue (removes the separate split kernel + fp32 O round-trip).
// ----------------------------------------------------------------------------
#define PAD 68
#define SK_OFF   0
#define SV_OFF   (64 * PAD)
#define SP_OFF   (2 * 64 * PAD)
#define ATTN_SMEM_FLOATS (3 * 64 * PAD)
#define ATTN_SMEM_BYTES  (ATTN_SMEM_FLOATS * 4)

__global__ __launch_bounds__(128) void attn_mma(
    const float* __restrict__ q, const float* __restrict__ k,
    const float* __restrict__ v,
    __nv_bfloat16* __restrict__ oh, __nv_bfloat16* __restrict__ ol)
{
    extern __shared__ float sm[];
    float* sK = sm + SK_OFF;
    float* sV = sm + SV_OFF;
    float* sP = sm + SP_OFF;

    const int tid  = threadIdx.x;
    const int lane = tid & 31;
    const int warp = tid >> 5;          // 0..3
    const int gid  = lane >> 2;
    const int tig  = lane & 3;
    const int bh = blockIdx.y;
    const int q0 = blockIdx.x * 64;
    const size_t bhoff = (size_t)bh * L_ * D_;
    const float* Q = q + bhoff;
    const float* K = k + bhoff;
    const float* V = v + bhoff;

    const float QSCALE = 0.125f * 1.4426950408889634f;

    const int r0 = q0 + warp * 16 + gid;
    uint32_t qf[8][4];
#pragma unroll
    for (int kk = 0; kk < 8; kk++) {
        qf[kk][0] = f2tf32(Q[(size_t)r0 * D_ + kk * 8 + tig] * QSCALE);
        qf[kk][1] = f2tf32(Q[(size_t)(r0 + 8) * D_ + kk * 8 + tig] * QSCALE);
        qf[kk][2] = f2tf32(Q[(size_t)r0 * D_ + kk * 8 + tig + 4] * QSCALE);
        qf[kk][3] = f2tf32(Q[(size_t)(r0 + 8) * D_ + kk * 8 + tig + 4] * QSCALE);
    }

    float of[8][4];
#pragma unroll
    for (int nt = 0; nt < 8; nt++)
#pragma unroll
        for (int j = 0; j < 4; j++) of[nt][j] = 0.f;

    float m0 = -INFINITY, m1 = -INFINITY;
    float l0 = 0.f, l1 = 0.f;

    uint32_t* sPw = (uint32_t*)(sP + warp * 16 * PAD);

    for (int c0 = 0; c0 < L_; c0 += 64) {
#pragma unroll
        for (int it = 0; it < 8; it++) {
            int idx = tid + it * 128;
            int r = idx >> 4;
            int c4 = idx & 15;
            float4 a = *(const float4*)(K + (size_t)(c0 + r) * D_ + c4 * 4);
            uint4 ua = {f2tf32(a.x), f2tf32(a.y), f2tf32(a.z), f2tf32(a.w)};
            *(uint4*)(&sK[r * PAD + c4 * 4]) = ua;
            float4 bv = *(const float4*)(V + (size_t)(c0 + r) * D_ + c4 * 4);
            uint4 ub = {f2tf32(bv.x), f2tf32(bv.y), f2tf32(bv.z), f2tf32(bv.w)};
            *(uint4*)(&sV[r * PAD + c4 * 4]) = ub;
        }
        __syncthreads();

        float sf[8][4];
#pragma unroll
        for (int nt = 0; nt < 8; nt++)
#pragma unroll
            for (int j = 0; j < 4; j++) sf[nt][j] = 0.f;

        const uint32_t* sKu = (const uint32_t*)sK;
#pragma unroll
        for (int kk = 0; kk < 8; kk++) {
#pragma unroll
            for (int nt = 0; nt < 8; nt++) {
                uint32_t b0 = sKu[(nt * 8 + gid) * PAD + kk * 8 + tig];
                uint32_t b1 = sKu[(nt * 8 + gid) * PAD + kk * 8 + tig + 4];
                mma_tf32(sf[nt], qf[kk], b0, b1);
            }
        }

        float mn0 = m0, mn1 = m1;
#pragma unroll
        for (int nt = 0; nt < 8; nt++) {
            mn0 = fmaxf(mn0, fmaxf(sf[nt][0], sf[nt][1]));
            mn1 = fmaxf(mn1, fmaxf(sf[nt][2], sf[nt][3]));
        }
        mn0 = fmaxf(mn0, __shfl_xor_sync(0xffffffffu, mn0, 1));
        mn0 = fmaxf(mn0, __shfl_xor_sync(0xffffffffu, mn0, 2));
        mn1 = fmaxf(mn1, __shfl_xor_sync(0xffffffffu, mn1, 1));
        mn1 = fmaxf(mn1, __shfl_xor_sync(0xffffffffu, mn1, 2));
        float a0 = exp2f(m0 - mn0);
        float a1 = exp2f(m1 - mn1);
        m0 = mn0; m1 = mn1;
        l0 *= a0; l1 *= a1;

#pragma unroll
        for (int nt = 0; nt < 8; nt++) {
            float p00 = exp2f(sf[nt][0] - m0);
            float p01 = exp2f(sf[nt][1] - m0);
            float p10 = exp2f(sf[nt][2] - m1);
            float p11 = exp2f(sf[nt][3] - m1);
            l0 += p00 + p01;
            l1 += p10 + p11;
            uint2 u0 = {f2tf32(p00), f2tf32(p01)};
            uint2 u1 = {f2tf32(p10), f2tf32(p11)};
            *(uint2*)(&sPw[gid * PAD + nt * 8 + 2 * tig]) = u0;
            *(uint2*)(&sPw[(gid + 8) * PAD + nt * 8 + 2 * tig]) = u1;
            of[nt][0] *= a0; of[nt][1] *= a0;
            of[nt][2] *= a1; of[nt][3] *= a1;
        }
        __syncwarp();

        const uint32_t* sVu = (const uint32_t*)sV;
#pragma unroll
        for (int kk = 0; kk < 8; kk++) {
            uint32_t af[4];
            af[0] = sPw[gid * PAD + kk * 8 + tig];
            af[1] = sPw[(gid + 8) * PAD + kk * 8 + tig];
            af[2] = sPw[gid * PAD + kk * 8 + tig + 4];
            af[3] = sPw[(gid + 8) * PAD + kk * 8 + tig + 4];
#pragma unroll
            for (int nt = 0; nt < 8; nt++) {
                uint32_t b0 = sVu[(kk * 8 + tig) * PAD + nt * 8 + gid];
                uint32_t b1 = sVu[(kk * 8 + tig + 4) * PAD + nt * 8 + gid];
                mma_tf32(of[nt], af, b0, b1);
            }
        }
        __syncthreads();
    }

    // ---- epilogue: normalize + fused bf16 hi/lo split, [B,L,H,D] ----
    l0 += __shfl_xor_sync(0xffffffffu, l0, 1);
    l0 += __shfl_xor_sync(0xffffffffu, l0, 2);
    l1 += __shfl_xor_sync(0xffffffffu, l1, 1);
    l1 += __shfl_xor_sync(0xffffffffu, l1, 2);
    const float inv0 = 1.f / l0;
    const float inv1 = 1.f / l1;

    const int b = bh >> 4;
    const int h = bh & 15;
    const size_t row0 = (((size_t)(b * L_ + r0)) * H_ + h) * D_;
    const size_t row1 = (((size_t)(b * L_ + r0 + 8)) * H_ + h) * D_;
#pragma unroll
    for (int nt = 0; nt < 8; nt++) {
        float v00 = of[nt][0] * inv0, v01 = of[nt][1] * inv0;
        float v10 = of[nt][2] * inv1, v11 = of[nt][3] * inv1;
        __nv_bfloat16 h0, l0b, h1, l1b, h2, l2b, h3, l3b;
        bfsplit(v00, h0, l0b); bfsplit(v01, h1, l1b);
        bfsplit(v10, h2, l2b); bfsplit(v11, h3, l3b);
        uint32_t ph0 = (uint32_t)__bfloat16_as_ushort(h0) | ((uint32_t)__bfloat16_as_ushort(h1) << 16);
        uint32_t pl0 = (uint32_t)__bfloat16_as_ushort(l0b) | ((uint32_t)__bfloat16_as_ushort(l1b) << 16);
        uint32_t ph1 = (uint32_t)__bfloat16_as_ushort(h2) | ((uint32_t)__bfloat16_as_ushort(h3) << 16);
        uint32_t pl1 = (uint32_t)__bfloat16_as_ushort(l2b) | ((uint32_t)__bfloat16_as_ushort(l3b) << 16);
        *(uint32_t*)(oh + row0 + nt * 8 + 2 * tig) = ph0;
        *(uint32_t*)(ol + row0 + nt * 8 + 2 * tig) = pl0;
        *(uint32_t*)(oh + row1 + nt * 8 + 2 * tig) = ph1;
        *(uint32_t*)(ol + row1 + nt * 8 + 2 * tig) = pl1;
    }
}

// ----------------------------------------------------------------------------
// Launch
// ----------------------------------------------------------------------------
extern "C" void kernel_launch(void* const* d_in, const int* in_sizes, int n_in,
                              void* d_out, int out_size)
{
    const float* x      = (const float*)d_in[0];
    const float* pe     = (const float*)d_in[1];
    const float* w_qkv  = (const float*)d_in[2];
    const float* qscale = (const float*)d_in[3];
    const float* kscale = (const float*)d_in[4];
    const float* w_proj = (const float*)d_in[5];
    const float* b_proj = (const float*)d_in[6];
    float* out = (float*)d_out;

    float *p_qkv, *p_q, *p_k, *p_v;
    cudaGetSymbolAddress((void**)&p_qkv, g_qkv);
    cudaGetSymbolAddress((void**)&p_q, g_q);
    cudaGetSymbolAddress((void**)&p_k, g_k);
    cudaGetSymbolAddress((void**)&p_v, g_v);

    __nv_bfloat16 *p_xh, *p_xl, *p_wqh, *p_wql, *p_wph, *p_wpl, *p_oh, *p_ol;
    cudaGetSymbolAddress((void**)&p_xh, g_xh);
    cudaGetSymbolAddress((void**)&p_xl, g_xl);
    cudaGetSymbolAddress((void**)&p_wqh, g_wqh);
    cudaGetSymbolAddress((void**)&p_wql, g_wql);
    cudaGetSymbolAddress((void**)&p_wph, g_wph);
    cudaGetSymbolAddress((void**)&p_wpl, g_wpl);
    cudaGetSymbolAddress((void**)&p_oh, g_oh);
    cudaGetSymbolAddress((void**)&p_ol, g_ol);

    cudaFuncSetAttribute(attn_mma, cudaFuncAttributeMaxDynamicSharedMemorySize,
                         ATTN_SMEM_BYTES);
    cudaFuncSetAttribute(gemm_bf16s, cudaFuncAttributeMaxDynamicSharedMemorySize,
                         GEMM_SMEM_BYTES);

    // 0a. split x -> bf16 hi/lo
    split_kernel<<<BL_ * DIM_ / 1024, 256>>>(x, p_xh, p_xl, BL_ * DIM_);
    // 0b. transpose+split weights
    {
        dim3 gq(3 * DIM_ / 32, DIM_ / 32);
        tsplit_kernel<<<gq, 256>>>(w_qkv, p_wqh, p_wql, DIM_, 3 * DIM_);
        dim3 gp(DIM_ / 32, DIM_ / 32);
        tsplit_kernel<<<gp, 256>>>(w_proj, p_wph, p_wpl, DIM_, DIM_);
    }
    // 1. QKV GEMM (bf16 3-term, ldmatrix): [4096,1024] @ [1024,3072]
    {
        dim3 grid(3 * DIM_ / 128, BL_ / 128);
        gemm_bf16s<<<grid, 256, GEMM_SMEM_BYTES>>>(p_xh, p_xl, p_wqh, p_wql,
                                                   nullptr, p_qkv,
                                                   BL_, 3 * DIM_, DIM_);
    }
    // 2. RMSNorm + RoPE + split
    {
        int warps = B_ * H_ * L_;
        rmsrope_kernel<<<warps * 32 / 256, 256>>>(p_qkv, pe, qscale, kscale,
                                                  p_q, p_k, p_v);
    }
    // 3. Attention (tf32 mma, 64 queries/block, fused split epilogue)
    {
        dim3 grid(L_ / 64, BH_);
        attn_mma<<<grid, 128, ATTN_SMEM_BYTES>>>(p_q, p_k, p_v, p_oh, p_ol);
    }
    // 4. Output projection (bf16 3-term) + bias
    {
        dim3 grid(DIM_ / 128, BL_ / 128);
        gemm_bf16s<<<grid, 256, GEMM_SMEM_BYTES>>>(p_oh, p_ol, p_wph, p_wpl,
                                                   b_proj, out,
                                                   BL_, DIM_, DIM_);
    }
}

// round 13
// speedup vs baseline: 1.1489x; 1.0190x over previous
#include <cuda_runtime.h>
#include <cuda_bf16.h>
#include <math.h>
#include <stdint.h>

// ----------------------------------------------------------------------------
// Problem constants
// ----------------------------------------------------------------------------
#define B_   2
#define L_   2048
#define DIM_ 1024
#define H_   16
#define D_   64
#define BL_  (B_ * L_)         // 4096
#define BH_  (B_ * H_)         // 32

// Scratch (device globals — allocation-free per harness rules)
__device__ float g_qkv[BL_ * 3 * DIM_];                // [4096, 3072]
__device__ float g_q[BH_ * L_ * D_];                   // [B,H,L,D] fp32
__device__ float g_k[BH_ * L_ * D_];                   // tf32-valued fp32
__device__ float g_v[BH_ * L_ * D_];                   // tf32-valued fp32

// bf16 hi/lo split operands
__device__ __nv_bfloat16 g_xh[BL_ * DIM_], g_xl[BL_ * DIM_];          // x
__device__ __nv_bfloat16 g_wqh[3 * DIM_ * DIM_], g_wql[3 * DIM_ * DIM_]; // w_qkv^T
__device__ __nv_bfloat16 g_wph[DIM_ * DIM_], g_wpl[DIM_ * DIM_];      // w_proj^T
__device__ __nv_bfloat16 g_oh[BL_ * DIM_], g_ol[BL_ * DIM_];          // attn out split

// ----------------------------------------------------------------------------
// helpers
// ----------------------------------------------------------------------------
__device__ __forceinline__ uint32_t f2tf32(float x) {
    uint32_t r;
    asm("cvt.rna.tf32.f32 %0, %1;" : "=r"(r) : "f"(x));
    return r;
}

__device__ __forceinline__ void mma_tf32(float* d, const uint32_t* a,
                                         uint32_t b0, uint32_t b1) {
    asm volatile(
        "mma.sync.aligned.m16n8k8.row.col.f32.tf32.tf32.f32 "
        "{%0,%1,%2,%3}, {%4,%5,%6,%7}, {%8,%9}, {%0,%1,%2,%3};\n"
        : "+f"(d[0]), "+f"(d[1]), "+f"(d[2]), "+f"(d[3])
        : "r"(a[0]), "r"(a[1]), "r"(a[2]), "r"(a[3]), "r"(b0), "r"(b1));
}

__device__ __forceinline__ void mma_bf16(float* d, const uint32_t* a,
                                         uint32_t b0, uint32_t b1) {
    asm volatile(
        "mma.sync.aligned.m16n8k16.row.col.f32.bf16.bf16.f32 "
        "{%0,%1,%2,%3}, {%4,%5,%6,%7}, {%8,%9}, {%0,%1,%2,%3};\n"
        : "+f"(d[0]), "+f"(d[1]), "+f"(d[2]), "+f"(d[3])
        : "r"(a[0]), "r"(a[1]), "r"(a[2]), "r"(a[3]), "r"(b0), "r"(b1));
}

__device__ __forceinline__ void ldsm_x4(uint32_t* r, uint32_t addr) {
    asm volatile("ldmatrix.sync.aligned.m8n8.x4.shared.b16 {%0,%1,%2,%3}, [%4];"
                 : "=r"(r[0]), "=r"(r[1]), "=r"(r[2]), "=r"(r[3]) : "r"(addr));
}

__device__ __forceinline__ void cpa16(uint32_t dst, const void* src) {
    asm volatile("cp.async.cg.shared.global [%0], [%1], 16;"
                 :: "r"(dst), "l"(src));
}
#define CP_COMMIT() asm volatile("cp.async.commit_group;" ::: "memory")
#define CP_WAIT0()  asm volatile("cp.async.wait_group 0;" ::: "memory")
#define CP_WAIT1()  asm volatile("cp.async.wait_group 1;" ::: "memory")

__device__ __forceinline__ void bfsplit(float v, __nv_bfloat16& h, __nv_bfloat16& l) {
    h = __float2bfloat16(v);
    l = __float2bfloat16(v - __bfloat162float(h));
}

// ----------------------------------------------------------------------------
// Elementwise hi/lo split: fp32 -> bf16 hi + bf16 lo
// ----------------------------------------------------------------------------
__global__ __launch_bounds__(256) void split_kernel(
    const float* __restrict__ s, __nv_bfloat16* __restrict__ hi,
    __nv_bfloat16* __restrict__ lo, int n)
{
    int i = (blockIdx.x * blockDim.x + threadIdx.x) * 4;
    if (i >= n) return;
    float4 v = *(const float4*)(s + i);
    __nv_bfloat16 h[4], l[4];
    bfsplit(v.x, h[0], l[0]);
    bfsplit(v.y, h[1], l[1]);
    bfsplit(v.z, h[2], l[2]);
    bfsplit(v.w, h[3], l[3]);
    uint2 ph, pl;
    ph.x = (uint32_t)__bfloat16_as_ushort(h[0]) | ((uint32_t)__bfloat16_as_ushort(h[1]) << 16);
    ph.y = (uint32_t)__bfloat16_as_ushort(h[2]) | ((uint32_t)__bfloat16_as_ushort(h[3]) << 16);
    pl.x = (uint32_t)__bfloat16_as_ushort(l[0]) | ((uint32_t)__bfloat16_as_ushort(l[1]) << 16);
    pl.y = (uint32_t)__bfloat16_as_ushort(l[2]) | ((uint32_t)__bfloat16_as_ushort(l[3]) << 16);
    *(uint2*)(hi + i) = ph;
    *(uint2*)(lo + i) = pl;
}

// ----------------------------------------------------------------------------
// Transpose + split: w[K][N] fp32 -> th/tl[N][K] bf16
// ----------------------------------------------------------------------------
__global__ __launch_bounds__(256) void tsplit_kernel(
    const float* __restrict__ w, __nv_bfloat16* __restrict__ th,
    __nv_bfloat16* __restrict__ tl, int K, int N)
{
    __shared__ float tile[32][33];
    const int t = threadIdx.x;
    const int k0 = blockIdx.y * 32;
    const int n0 = blockIdx.x * 32;
    const int rr = t >> 5;
    const int cc = t & 31;
#pragma unroll
    for (int i = 0; i < 4; i++)
        tile[rr + i * 8][cc] = w[(size_t)(k0 + rr + i * 8) * N + n0 + cc];
    __syncthreads();
#pragma unroll
    for (int i = 0; i < 4; i++) {
        int r = rr + i * 8;
        float v = tile[cc][r];
        __nv_bfloat16 h, l;
        bfsplit(v, h, l);
        th[(size_t)(n0 + r) * K + k0 + cc] = h;
        tl[(size_t)(n0 + r) * K + k0 + cc] = l;
    }
}

// ----------------------------------------------------------------------------
// bf16 3-term GEMM with ldmatrix fragment loads. C = A @ B^T (+bias).
// Unchanged (proven: QKV 219us, tensor 58%).
// ----------------------------------------------------------------------------
#define ROWW 20                    // row stride in 32-bit words (40 bf16)
#define ARRW (128 * ROWW)
#define STW  (4 * ARRW)
#define GEMM_SMEM_BYTES (2 * STW * 4)   // 81920

__global__ __launch_bounds__(256, 2) void gemm_bf16s(
    const __nv_bfloat16* __restrict__ Ah, const __nv_bfloat16* __restrict__ Al,
    const __nv_bfloat16* __restrict__ Bh, const __nv_bfloat16* __restrict__ Bl,
    const float* __restrict__ bias, float* __restrict__ C,
    int M, int N, int K)
{
    extern __shared__ float sm[];
    const uint32_t smem_u32 = (uint32_t)__cvta_generic_to_shared(sm);

    const int tid  = threadIdx.x;
    const int lane = tid & 31;
    const int warp = tid >> 5;
    const int gid  = lane >> 2;
    const int tig  = lane & 3;
    const int warpm = warp & 1;
    const int warpn = warp >> 1;
    const int row0 = blockIdx.y * 128;
    const int col0 = blockIdx.x * 128;

    const int arr = tid >> 6;
    const int g   = tid & 63;
    const int seg = g & 3;
    const int r0s = g >> 2;
    const __nv_bfloat16* sb =
        (arr == 0) ? Ah : (arr == 1) ? Al : (arr == 2) ? Bh : Bl;
    const int tile0 = (arr < 2) ? row0 : col0;
    const __nv_bfloat16* srcbase = sb + (size_t)(tile0 + r0s) * K + seg * 8;
    const uint32_t dstbase = smem_u32 + (uint32_t)(arr * ARRW + r0s * ROWW) * 4u
                             + (uint32_t)seg * 16u;

    const int lm  = lane & 7;
    const int sel = lane >> 3;
    const uint32_t aoff = (uint32_t)(((warpm * 64 + (sel & 1) * 8 + lm) * ROWW
                                      + (sel >> 1) * 4) * 4);
    const uint32_t boff = (uint32_t)(((warpn * 32 + (sel >> 1) * 8 + lm) * ROWW
                                      + (sel & 1) * 4) * 4);

    float acc[4][4][4];
#pragma unroll
    for (int mt = 0; mt < 4; mt++)
#pragma unroll
        for (int nt = 0; nt < 4; nt++)
#pragma unroll
            for (int j = 0; j < 4; j++) acc[mt][nt][j] = 0.f;

    const int nch = K >> 5;

#pragma unroll
    for (int it = 0; it < 8; it++)
        cpa16(dstbase + (uint32_t)(it * 16 * ROWW) * 4u,
              srcbase + (size_t)(it * 16) * K);
    CP_COMMIT();

    for (int ch = 0; ch < nch; ch++) {
        if (ch + 1 < nch) {
            uint32_t db = dstbase + (uint32_t)(((ch + 1) & 1) * STW) * 4u;
            const __nv_bfloat16* srck = srcbase + (ch + 1) * 32;
#pragma unroll
            for (int it = 0; it < 8; it++)
                cpa16(db + (uint32_t)(it * 16 * ROWW) * 4u,
                      srck + (size_t)(it * 16) * K);
            CP_COMMIT();
            CP_WAIT1();
        } else {
            CP_WAIT0();
        }
        __syncthreads();

        const uint32_t sbase = smem_u32 + (uint32_t)((ch & 1) * STW) * 4u;

#pragma unroll
        for (int ks = 0; ks < 2; ks++) {
            const uint32_t kb = (uint32_t)(ks * 32);
            uint32_t ah[4][4], al[4][4];
#pragma unroll
            for (int mt = 0; mt < 4; mt++) {
                uint32_t ao = sbase + aoff + (uint32_t)(mt * 16 * ROWW) * 4u + kb;
                ldsm_x4(ah[mt], ao);
                ldsm_x4(al[mt], ao + (uint32_t)(ARRW * 4));
            }
#pragma unroll
            for (int p = 0; p < 2; p++) {
                uint32_t bo = sbase + boff + (uint32_t)((2 * ARRW + p * 16 * ROWW) * 4) + kb;
                uint32_t bhp[4], blp[4];
                ldsm_x4(bhp, bo);
                ldsm_x4(blp, bo + (uint32_t)(ARRW * 4));
#pragma unroll
                for (int q = 0; q < 2; q++) {
                    const int nt = p * 2 + q;
                    uint32_t bh0 = bhp[q * 2], bh1 = bhp[q * 2 + 1];
                    uint32_t bl0 = blp[q * 2], bl1 = blp[q * 2 + 1];
#pragma unroll
                    for (int mt = 0; mt < 4; mt++) {
                        mma_bf16(acc[mt][nt], al[mt], bh0, bh1);
                        mma_bf16(acc[mt][nt], ah[mt], bl0, bl1);
                        mma_bf16(acc[mt][nt], ah[mt], bh0, bh1);
                    }
                }
            }
        }
        __syncthreads();
    }

#pragma unroll
    for (int mt = 0; mt < 4; mt++) {
        int gr = row0 + warpm * 64 + mt * 16 + gid;
#pragma unroll
        for (int nt = 0; nt < 4; nt++) {
            int gc = col0 + warpn * 32 + nt * 8 + 2 * tig;
            float b0 = 0.f, b1 = 0.f;
            if (bias) { b0 = bias[gc]; b1 = bias[gc + 1]; }
            float2 c01 = {acc[mt][nt][0] + b0, acc[mt][nt][1] + b1};
            float2 c23 = {acc[mt][nt][2] + b0, acc[mt][nt][3] + b1};
            *(float2*)(C + (size_t)gr * N + gc) = c01;
            *(float2*)(C + (size_t)(gr + 8) * N + gc) = c23;
        }
    }
}

// ----------------------------------------------------------------------------
// RMSNorm (over D=64) + RoPE; split qkv into q/k/v in [B,H,L,D].
// K and V are written pre-rounded to tf32 (bit-identical to converting at
// attention staging time) so attention can stage with raw cp.async copies.
// ----------------------------------------------------------------------------
__global__ __launch_bounds__(256) void rmsrope_kernel(
    const float* __restrict__ qkv, const float* __restrict__ pe,
    const float* __restrict__ qscale, const float* __restrict__ kscale,
    float* __restrict__ q, float* __restrict__ k, float* __restrict__ v)
{
    const int warp = (blockIdx.x * blockDim.x + threadIdx.x) >> 5;
    const int lane = threadIdx.x & 31;
    const int b = warp >> 15;
    const int rem = warp & 32767;
    const int h = rem >> 11;
    const int l = rem & 2047;

    const float* base = qkv + ((size_t)(b * L_ + l)) * (3 * DIM_) + h * D_;
    float2 q2 = *(const float2*)(base + lane * 2);
    float2 k2 = *(const float2*)(base + DIM_ + lane * 2);
    float2 v2 = *(const float2*)(base + 2 * DIM_ + lane * 2);

    float sq = q2.x * q2.x + q2.y * q2.y;
    float sk = k2.x * k2.x + k2.y * k2.y;
#pragma unroll
    for (int o = 16; o > 0; o >>= 1) {
        sq += __shfl_xor_sync(0xffffffffu, sq, o);
        sk += __shfl_xor_sync(0xffffffffu, sk, o);
    }
    const float qinv = rsqrtf(sq * (1.f / 64.f) + 1e-6f);
    const float kinv = rsqrtf(sk * (1.f / 64.f) + 1e-6f);

    float2 qsc = *(const float2*)(qscale + lane * 2);
    float2 ksc = *(const float2*)(kscale + lane * 2);
    float t0 = q2.x * qinv * qsc.x;
    float t1 = q2.y * qinv * qsc.y;
    float u0 = k2.x * kinv * ksc.x;
    float u1 = k2.y * kinv * ksc.y;

    float4 p = *(const float4*)(pe + (((size_t)(b * L_ + l)) * 32 + lane) * 4);
    float2 qo, ko;
    qo.x = p.x * t0 + p.y * t1;
    qo.y = p.z * t0 + p.w * t1;
    ko.x = p.x * u0 + p.y * u1;
    ko.y = p.z * u0 + p.w * u1;

    const size_t orow = ((size_t)((b * H_ + h) * L_ + l)) * D_;
    *(float2*)(q + orow + lane * 2) = qo;
    uint2 kt = {f2tf32(ko.x), f2tf32(ko.y)};
    uint2 vt = {f2tf32(v2.x), f2tf32(v2.y)};
    *(uint2*)(k + orow + lane * 2) = kt;
    *(uint2*)(v + orow + lane * 2) = vt;
}

// ----------------------------------------------------------------------------
// Flash attention (tf32 mma), 4 warps / 64 queries per block. K/V arrive
// pre-converted to tf32 -> staging is a pure cp.async byte copy, ping-pong
// double-buffered so LDG latency overlaps compute.
// ----------------------------------------------------------------------------
#define PAD 68
#define TILEF (64 * PAD)                 // floats per K or V buffer
#define SP_OFF (4 * TILEF)
#define ATTN_SMEM_FLOATS (4 * TILEF + 4 * 16 * PAD)
#define ATTN_SMEM_BYTES  (ATTN_SMEM_FLOATS * 4)   // 87040

__global__ __launch_bounds__(128) void attn_mma(
    const float* __restrict__ q, const float* __restrict__ k,
    const float* __restrict__ v,
    __nv_bfloat16* __restrict__ oh, __nv_bfloat16* __restrict__ ol)
{
    extern __shared__ float sm[];
    const uint32_t smem_u32 = (uint32_t)__cvta_generic_to_shared(sm);
    float* sP = sm + SP_OFF;

    const int tid  = threadIdx.x;
    const int lane = tid & 31;
    const int warp = tid >> 5;          // 0..3
    const int gid  = lane >> 2;
    const int tig  = lane & 3;
    const int bh = blockIdx.y;
    const int q0 = blockIdx.x * 64;
    const size_t bhoff = (size_t)bh * L_ * D_;
    const float* Q = q + bhoff;
    const float* K = k + bhoff;
    const float* V = v + bhoff;

    const float QSCALE = 0.125f * 1.4426950408889634f;

    // staging role: thread covers (r, c4) pairs; 8 iters cover 64x64 K + V
    const int sr  = tid >> 4;           // 0..7 (rows sr + 8*it)
    const int sc4 = tid & 15;           // float4 col
    const uint32_t sdst = (uint32_t)((sr * PAD + sc4 * 4) * 4);
    const float* ksrc = K + (size_t)sr * D_ + sc4 * 4;
    const float* vsrc = V + (size_t)sr * D_ + sc4 * 4;

    const int r0 = q0 + warp * 16 + gid;
    uint32_t qf[8][4];
#pragma unroll
    for (int kk = 0; kk < 8; kk++) {
        qf[kk][0] = f2tf32(Q[(size_t)r0 * D_ + kk * 8 + tig] * QSCALE);
        qf[kk][1] = f2tf32(Q[(size_t)(r0 + 8) * D_ + kk * 8 + tig] * QSCALE);
        qf[kk][2] = f2tf32(Q[(size_t)r0 * D_ + kk * 8 + tig + 4] * QSCALE);
        qf[kk][3] = f2tf32(Q[(size_t)(r0 + 8) * D_ + kk * 8 + tig + 4] * QSCALE);
    }

    float of[8][4];
#pragma unroll
    for (int nt = 0; nt < 8; nt++)
#pragma unroll
        for (int j = 0; j < 4; j++) of[nt][j] = 0.f;

    float m0 = -INFINITY, m1 = -INFINITY;
    float l0 = 0.f, l1 = 0.f;

    uint32_t* sPw = (uint32_t*)(sP + warp * 16 * PAD);

    const int ntiles = L_ / 64;

    // prologue: stage tile 0 into buffer 0
#pragma unroll
    for (int it = 0; it < 8; it++) {
        cpa16(smem_u32 + sdst + (uint32_t)(it * 8 * PAD * 4),
              ksrc + (size_t)(it * 8) * D_);
        cpa16(smem_u32 + (uint32_t)(2 * TILEF * 4) + sdst + (uint32_t)(it * 8 * PAD * 4),
              vsrc + (size_t)(it * 8) * D_);
    }
    CP_COMMIT();

    for (int t = 0; t < ntiles; t++) {
        if (t + 1 < ntiles) {
            const uint32_t bb = (uint32_t)(((t + 1) & 1) * TILEF * 4);
            const float* kn = ksrc + (size_t)(t + 1) * 64 * D_;
            const float* vn = vsrc + (size_t)(t + 1) * 64 * D_;
#pragma unroll
            for (int it = 0; it < 8; it++) {
                cpa16(smem_u32 + bb + sdst + (uint32_t)(it * 8 * PAD * 4),
                      kn + (size_t)(it * 8) * D_);
                cpa16(smem_u32 + (uint32_t)(2 * TILEF * 4) + bb + sdst + (uint32_t)(it * 8 * PAD * 4),
                      vn + (size_t)(it * 8) * D_);
            }
            CP_COMMIT();
            CP_WAIT1();
        } else {
            CP_WAIT0();
        }
        __syncthreads();

        const uint32_t* sKu = (const uint32_t*)(sm + (t & 1) * TILEF);
        const uint32_t* sVu = (const uint32_t*)(sm + 2 * TILEF + (t & 1) * TILEF);

        // ---- S = Q K^T ----
        float sf[8][4];
#pragma unroll
        for (int nt = 0; nt < 8; nt++)
#pragma unroll
            for (int j = 0; j < 4; j++) sf[nt][j] = 0.f;

#pragma unroll
        for (int kk = 0; kk < 8; kk++) {
#pragma unroll
            for (int nt = 0; nt < 8; nt++) {
                uint32_t b0 = sKu[(nt * 8 + gid) * PAD + kk * 8 + tig];
                uint32_t b1 = sKu[(nt * 8 + gid) * PAD + kk * 8 + tig + 4];
                mma_tf32(sf[nt], qf[kk], b0, b1);
            }
        }

        // ---- online softmax in registers ----
        float mn0 = m0, mn1 = m1;
#pragma unroll
        for (int nt = 0; nt < 8; nt++) {
            mn0 = fmaxf(mn0, fmaxf(sf[nt][0], sf[nt][1]));
            mn1 = fmaxf(mn1, fmaxf(sf[nt][2], sf[nt][3]));
        }
        mn0 = fmaxf(mn0, __shfl_xor_sync(0xffffffffu, mn0, 1));
        mn0 = fmaxf(mn0, __shfl_xor_sync(0xffffffffu, mn0, 2));
        mn1 = fmaxf(mn1, __shfl_xor_sync(0xffffffffu, mn1, 1));
        mn1 = fmaxf(mn1, __shfl_xor_sync(0xffffffffu, mn1, 2));
        float a0 = exp2f(m0 - mn0);
        float a1 = exp2f(m1 - mn1);
        m0 = mn0; m1 = mn1;
        l0 *= a0; l1 *= a1;

#pragma unroll
        for (int nt = 0; nt < 8; nt++) {
            float p00 = exp2f(sf[nt][0] - m0);
            float p01 = exp2f(sf[nt][1] - m0);
            float p10 = exp2f(sf[nt][2] - m1);
            float p11 = exp2f(sf[nt][3] - m1);
            l0 += p00 + p01;
            l1 += p10 + p11;
            uint2 u0 = {f2tf32(p00), f2tf32(p01)};
            uint2 u1 = {f2tf32(p10), f2tf32(p11)};
            *(uint2*)(&sPw[gid * PAD + nt * 8 + 2 * tig]) = u0;
            *(uint2*)(&sPw[(gid + 8) * PAD + nt * 8 + 2 * tig]) = u1;
            of[nt][0] *= a0; of[nt][1] *= a0;
            of[nt][2] *= a1; of[nt][3] *= a1;
        }
        __syncwarp();

        // ---- O += P @ V ----
#pragma unroll
        for (int kk = 0; kk < 8; kk++) {
            uint32_t af[4];
            af[0] = sPw[gid * PAD + kk * 8 + tig];
            af[1] = sPw[(gid + 8) * PAD + kk * 8 + tig];
            af[2] = sPw[gid * PAD + kk * 8 + tig + 4];
            af[3] = sPw[(gid + 8) * PAD + kk * 8 + tig + 4];
#pragma unroll
            for (int nt = 0; nt < 8; nt++) {
                uint32_t b0 = sVu[(kk * 8 + tig) * PAD + nt * 8 + gid];
                uint32_t b1 = sVu[(kk * 8 + tig + 4) * PAD + nt * 8 + gid];
                mma_tf32(of[nt], af, b0, b1);
            }
        }
        __syncthreads();
    }

    // ---- epilogue: normalize + fused bf16 hi/lo split, [B,L,H,D] ----
    l0 += __shfl_xor_sync(0xffffffffu, l0, 1);
    l0 += __shfl_xor_sync(0xffffffffu, l0, 2);
    l1 += __shfl_xor_sync(0xffffffffu, l1, 1);
    l1 += __shfl_xor_sync(0xffffffffu, l1, 2);
    const float inv0 = 1.f / l0;
    const float inv1 = 1.f / l1;

    const int b = bh >> 4;
    const int h = bh & 15;
    const size_t row0 = (((size_t)(b * L_ + r0)) * H_ + h) * D_;
    const size_t row1 = (((size_t)(b * L_ + r0 + 8)) * H_ + h) * D_;
#pragma unroll
    for (int nt = 0; nt < 8; nt++) {
        float v00 = of[nt][0] * inv0, v01 = of[nt][1] * inv0;
        float v10 = of[nt][2] * inv1, v11 = of[nt][3] * inv1;
        __nv_bfloat16 h0, l0b, h1, l1b, h2, l2b, h3, l3b;
        bfsplit(v00, h0, l0b); bfsplit(v01, h1, l1b);
        bfsplit(v10, h2, l2b); bfsplit(v11, h3, l3b);
        uint32_t ph0 = (uint32_t)__bfloat16_as_ushort(h0) | ((uint32_t)__bfloat16_as_ushort(h1) << 16);
        uint32_t pl0 = (uint32_t)__bfloat16_as_ushort(l0b) | ((uint32_t)__bfloat16_as_ushort(l1b) << 16);
        uint32_t ph1 = (uint32_t)__bfloat16_as_ushort(h2) | ((uint32_t)__bfloat16_as_ushort(h3) << 16);
        uint32_t pl1 = (uint32_t)__bfloat16_as_ushort(l2b) | ((uint32_t)__bfloat16_as_ushort(l3b) << 16);
        *(uint32_t*)(oh + row0 + nt * 8 + 2 * tig) = ph0;
        *(uint32_t*)(ol + row0 + nt * 8 + 2 * tig) = pl0;
        *(uint32_t*)(oh + row1 + nt * 8 + 2 * tig) = ph1;
        *(uint32_t*)(ol + row1 + nt * 8 + 2 * tig) = pl1;
    }
}

// ----------------------------------------------------------------------------
// Launch
// ----------------------------------------------------------------------------
extern "C" void kernel_launch(void* const* d_in, const int* in_sizes, int n_in,
                              void* d_out, int out_size)
{
    const float* x      = (const float*)d_in[0];
    const float* pe     = (const float*)d_in[1];
    const float* w_qkv  = (const float*)d_in[2];
    const float* qscale = (const float*)d_in[3];
    const float* kscale = (const float*)d_in[4];
    const float* w_proj = (const float*)d_in[5];
    const float* b_proj = (const float*)d_in[6];
    float* out = (float*)d_out;

    float *p_qkv, *p_q, *p_k, *p_v;
    cudaGetSymbolAddress((void**)&p_qkv, g_qkv);
    cudaGetSymbolAddress((void**)&p_q, g_q);
    cudaGetSymbolAddress((void**)&p_k, g_k);
    cudaGetSymbolAddress((void**)&p_v, g_v);

    __nv_bfloat16 *p_xh, *p_xl, *p_wqh, *p_wql, *p_wph, *p_wpl, *p_oh, *p_ol;
    cudaGetSymbolAddress((void**)&p_xh, g_xh);
    cudaGetSymbolAddress((void**)&p_xl, g_xl);
    cudaGetSymbolAddress((void**)&p_wqh, g_wqh);
    cudaGetSymbolAddress((void**)&p_wql, g_wql);
    cudaGetSymbolAddress((void**)&p_wph, g_wph);
    cudaGetSymbolAddress((void**)&p_wpl, g_wpl);
    cudaGetSymbolAddress((void**)&p_oh, g_oh);
    cudaGetSymbolAddress((void**)&p_ol, g_ol);

    cudaFuncSetAttribute(attn_mma, cudaFuncAttributeMaxDynamicSharedMemorySize,
                         ATTN_SMEM_BYTES);
    cudaFuncSetAttribute(gemm_bf16s, cudaFuncAttributeMaxDynamicSharedMemorySize,
                         GEMM_SMEM_BYTES);

    // 0a. split x -> bf16 hi/lo
    split_kernel<<<BL_ * DIM_ / 1024, 256>>>(x, p_xh, p_xl, BL_ * DIM_);
    // 0b. transpose+split weights
    {
        dim3 gq(3 * DIM_ / 32, DIM_ / 32);
        tsplit_kernel<<<gq, 256>>>(w_qkv, p_wqh, p_wql, DIM_, 3 * DIM_);
        dim3 gp(DIM_ / 32, DIM_ / 32);
        tsplit_kernel<<<gp, 256>>>(w_proj, p_wph, p_wpl, DIM_, DIM_);
    }
    // 1. QKV GEMM (bf16 3-term, ldmatrix): [4096,1024] @ [1024,3072]
    {
        dim3 grid(3 * DIM_ / 128, BL_ / 128);
        gemm_bf16s<<<grid, 256, GEMM_SMEM_BYTES>>>(p_xh, p_xl, p_wqh, p_wql,
                                                   nullptr, p_qkv,
                                                   BL_, 3 * DIM_, DIM_);
    }
    // 2. RMSNorm + RoPE + split (K/V pre-rounded to tf32)
    {
        int warps = B_ * H_ * L_;
        rmsrope_kernel<<<warps * 32 / 256, 256>>>(p_qkv, pe, qscale, kscale,
                                                  p_q, p_k, p_v);
    }
    // 3. Attention (tf32 mma, double-buffered cp.async staging)
    {
        dim3 grid(L_ / 64, BH_);
        attn_mma<<<grid, 128, ATTN_SMEM_BYTES>>>(p_q, p_k, p_v, p_oh, p_ol);
    }
    // 4. Output projection (bf16 3-term) + bias
    {
        dim3 grid(DIM_ / 128, BL_ / 128);
        gemm_bf16s<<<grid, 256, GEMM_SMEM_BYTES>>>(p_oh, p_ol, p_wph, p_wpl,
                                                   b_proj, out,
                                                   BL_, DIM_, DIM_);
    }
}

// round 15
// speedup vs baseline: 1.1637x; 1.0129x over previous
#include <cuda_runtime.h>
#include <cuda_bf16.h>
#include <math.h>
#include <stdint.h>

// ----------------------------------------------------------------------------
// Problem constants
// ----------------------------------------------------------------------------
#define B_   2
#define L_   2048
#define DIM_ 1024
#define H_   16
#define D_   64
#define BL_  (B_ * L_)         // 4096
#define BH_  (B_ * H_)         // 32

// Scratch (device globals — allocation-free per harness rules)
__device__ float g_qkv[BL_ * 3 * DIM_];                // [4096, 3072]
__device__ float g_q[BH_ * L_ * D_];                   // [B,H,L,D] fp32
__device__ float g_k[BH_ * L_ * D_];                   // tf32-valued fp32
__device__ float g_v[BH_ * L_ * D_];                   // tf32-valued fp32

// bf16 hi/lo split operands
__device__ __nv_bfloat16 g_xh[BL_ * DIM_], g_xl[BL_ * DIM_];          // x
__device__ __nv_bfloat16 g_wqh[3 * DIM_ * DIM_], g_wql[3 * DIM_ * DIM_]; // w_qkv^T
__device__ __nv_bfloat16 g_wph[DIM_ * DIM_], g_wpl[DIM_ * DIM_];      // w_proj^T
__device__ __nv_bfloat16 g_oh[BL_ * DIM_], g_ol[BL_ * DIM_];          // attn out split

// ----------------------------------------------------------------------------
// helpers
// ----------------------------------------------------------------------------
__device__ __forceinline__ uint32_t f2tf32(float x) {
    uint32_t r;
    asm("cvt.rna.tf32.f32 %0, %1;" : "=r"(r) : "f"(x));
    return r;
}

__device__ __forceinline__ void mma_tf32(float* d, const uint32_t* a,
                                         uint32_t b0, uint32_t b1) {
    asm volatile(
        "mma.sync.aligned.m16n8k8.row.col.f32.tf32.tf32.f32 "
        "{%0,%1,%2,%3}, {%4,%5,%6,%7}, {%8,%9}, {%0,%1,%2,%3};\n"
        : "+f"(d[0]), "+f"(d[1]), "+f"(d[2]), "+f"(d[3])
        : "r"(a[0]), "r"(a[1]), "r"(a[2]), "r"(a[3]), "r"(b0), "r"(b1));
}

__device__ __forceinline__ void mma_bf16(float* d, const uint32_t* a,
                                         uint32_t b0, uint32_t b1) {
    asm volatile(
        "mma.sync.aligned.m16n8k16.row.col.f32.bf16.bf16.f32 "
        "{%0,%1,%2,%3}, {%4,%5,%6,%7}, {%8,%9}, {%0,%1,%2,%3};\n"
        : "+f"(d[0]), "+f"(d[1]), "+f"(d[2]), "+f"(d[3])
        : "r"(a[0]), "r"(a[1]), "r"(a[2]), "r"(a[3]), "r"(b0), "r"(b1));
}

__device__ __forceinline__ void ldsm_x4(uint32_t* r, uint32_t addr) {
    asm volatile("ldmatrix.sync.aligned.m8n8.x4.shared.b16 {%0,%1,%2,%3}, [%4];"
                 : "=r"(r[0]), "=r"(r[1]), "=r"(r[2]), "=r"(r[3]) : "r"(addr));
}

__device__ __forceinline__ void cpa16(uint32_t dst, const void* src) {
    asm volatile("cp.async.cg.shared.global [%0], [%1], 16;"
                 :: "r"(dst), "l"(src));
}
#define CP_COMMIT() asm volatile("cp.async.commit_group;" ::: "memory")
#define CP_WAIT0()  asm volatile("cp.async.wait_group 0;" ::: "memory")
#define CP_WAIT1()  asm volatile("cp.async.wait_group 1;" ::: "memory")

__device__ __forceinline__ void bfsplit(float v, __nv_bfloat16& h, __nv_bfloat16& l) {
    h = __float2bfloat16(v);
    l = __float2bfloat16(v - __bfloat162float(h));
}

// ----------------------------------------------------------------------------
// Elementwise hi/lo split: fp32 -> bf16 hi + bf16 lo
// ----------------------------------------------------------------------------
__global__ __launch_bounds__(256) void split_kernel(
    const float* __restrict__ s, __nv_bfloat16* __restrict__ hi,
    __nv_bfloat16* __restrict__ lo, int n)
{
    int i = (blockIdx.x * blockDim.x + threadIdx.x) * 4;
    if (i >= n) return;
    float4 v = *(const float4*)(s + i);
    __nv_bfloat16 h[4], l[4];
    bfsplit(v.x, h[0], l[0]);
    bfsplit(v.y, h[1], l[1]);
    bfsplit(v.z, h[2], l[2]);
    bfsplit(v.w, h[3], l[3]);
    uint2 ph, pl;
    ph.x = (uint32_t)__bfloat16_as_ushort(h[0]) | ((uint32_t)__bfloat16_as_ushort(h[1]) << 16);
    ph.y = (uint32_t)__bfloat16_as_ushort(h[2]) | ((uint32_t)__bfloat16_as_ushort(h[3]) << 16);
    pl.x = (uint32_t)__bfloat16_as_ushort(l[0]) | ((uint32_t)__bfloat16_as_ushort(l[1]) << 16);
    pl.y = (uint32_t)__bfloat16_as_ushort(l[2]) | ((uint32_t)__bfloat16_as_ushort(l[3]) << 16);
    *(uint2*)(hi + i) = ph;
    *(uint2*)(lo + i) = pl;
}

// ----------------------------------------------------------------------------
// Transpose + split: w[K][N] fp32 -> th/tl[N][K] bf16
// ----------------------------------------------------------------------------
__global__ __launch_bounds__(256) void tsplit_kernel(
    const float* __restrict__ w, __nv_bfloat16* __restrict__ th,
    __nv_bfloat16* __restrict__ tl, int K, int N)
{
    __shared__ float tile[32][33];
    const int t = threadIdx.x;
    const int k0 = blockIdx.y * 32;
    const int n0 = blockIdx.x * 32;
    const int rr = t >> 5;
    const int cc = t & 31;
#pragma unroll
    for (int i = 0; i < 4; i++)
        tile[rr + i * 8][cc] = w[(size_t)(k0 + rr + i * 8) * N + n0 + cc];
    __syncthreads();
#pragma unroll
    for (int i = 0; i < 4; i++) {
        int r = rr + i * 8;
        float v = tile[cc][r];
        __nv_bfloat16 h, l;
        bfsplit(v, h, l);
        th[(size_t)(n0 + r) * K + k0 + cc] = h;
        tl[(size_t)(n0 + r) * K + k0 + cc] = l;
    }
}

// ----------------------------------------------------------------------------
// bf16 3-term GEMM with ldmatrix fragment loads. C = A @ B^T (+bias).
// Unchanged (proven: QKV 219us, tensor 58%).
// ----------------------------------------------------------------------------
#define ROWW 20                    // row stride in 32-bit words (40 bf16)
#define ARRW (128 * ROWW)
#define STW  (4 * ARRW)
#define GEMM_SMEM_BYTES (2 * STW * 4)   // 81920

__global__ __launch_bounds__(256, 2) void gemm_bf16s(
    const __nv_bfloat16* __restrict__ Ah, const __nv_bfloat16* __restrict__ Al,
    const __nv_bfloat16* __restrict__ Bh, const __nv_bfloat16* __restrict__ Bl,
    const float* __restrict__ bias, float* __restrict__ C,
    int M, int N, int K)
{
    extern __shared__ float sm[];
    const uint32_t smem_u32 = (uint32_t)__cvta_generic_to_shared(sm);

    const int tid  = threadIdx.x;
    const int lane = tid & 31;
    const int warp = tid >> 5;
    const int gid  = lane >> 2;
    const int tig  = lane & 3;
    const int warpm = warp & 1;
    const int warpn = warp >> 1;
    const int row0 = blockIdx.y * 128;
    const int col0 = blockIdx.x * 128;

    const int arr = tid >> 6;
    const int g   = tid & 63;
    const int seg = g & 3;
    const int r0s = g >> 2;
    const __nv_bfloat16* sb =
        (arr == 0) ? Ah : (arr == 1) ? Al : (arr == 2) ? Bh : Bl;
    const int tile0 = (arr < 2) ? row0 : col0;
    const __nv_bfloat16* srcbase = sb + (size_t)(tile0 + r0s) * K + seg * 8;
    const uint32_t dstbase = smem_u32 + (uint32_t)(arr * ARRW + r0s * ROWW) * 4u
                             + (uint32_t)seg * 16u;

    const int lm  = lane & 7;
    const int sel = lane >> 3;
    const uint32_t aoff = (uint32_t)(((warpm * 64 + (sel & 1) * 8 + lm) * ROWW
                                      + (sel >> 1) * 4) * 4);
    const uint32_t boff = (uint32_t)(((warpn * 32 + (sel >> 1) * 8 + lm) * ROWW
                                      + (sel & 1) * 4) * 4);

    float acc[4][4][4];
#pragma unroll
    for (int mt = 0; mt < 4; mt++)
#pragma unroll
        for (int nt = 0; nt < 4; nt++)
#pragma unroll
            for (int j = 0; j < 4; j++) acc[mt][nt][j] = 0.f;

    const int nch = K >> 5;

#pragma unroll
    for (int it = 0; it < 8; it++)
        cpa16(dstbase + (uint32_t)(it * 16 * ROWW) * 4u,
              srcbase + (size_t)(it * 16) * K);
    CP_COMMIT();

    for (int ch = 0; ch < nch; ch++) {
        if (ch + 1 < nch) {
            uint32_t db = dstbase + (uint32_t)(((ch + 1) & 1) * STW) * 4u;
            const __nv_bfloat16* srck = srcbase + (ch + 1) * 32;
#pragma unroll
            for (int it = 0; it < 8; it++)
                cpa16(db + (uint32_t)(it * 16 * ROWW) * 4u,
                      srck + (size_t)(it * 16) * K);
            CP_COMMIT();
            CP_WAIT1();
        } else {
            CP_WAIT0();
        }
        __syncthreads();

        const uint32_t sbase = smem_u32 + (uint32_t)((ch & 1) * STW) * 4u;

#pragma unroll
        for (int ks = 0; ks < 2; ks++) {
            const uint32_t kb = (uint32_t)(ks * 32);
            uint32_t ah[4][4], al[4][4];
#pragma unroll
            for (int mt = 0; mt < 4; mt++) {
                uint32_t ao = sbase + aoff + (uint32_t)(mt * 16 * ROWW) * 4u + kb;
                ldsm_x4(ah[mt], ao);
                ldsm_x4(al[mt], ao + (uint32_t)(ARRW * 4));
            }
#pragma unroll
            for (int p = 0; p < 2; p++) {
                uint32_t bo = sbase + boff + (uint32_t)((2 * ARRW + p * 16 * ROWW) * 4) + kb;
                uint32_t bhp[4], blp[4];
                ldsm_x4(bhp, bo);
                ldsm_x4(blp, bo + (uint32_t)(ARRW * 4));
#pragma unroll
                for (int q = 0; q < 2; q++) {
                    const int nt = p * 2 + q;
                    uint32_t bh0 = bhp[q * 2], bh1 = bhp[q * 2 + 1];
                    uint32_t bl0 = blp[q * 2], bl1 = blp[q * 2 + 1];
#pragma unroll
                    for (int mt = 0; mt < 4; mt++) {
                        mma_bf16(acc[mt][nt], al[mt], bh0, bh1);
                        mma_bf16(acc[mt][nt], ah[mt], bl0, bl1);
                        mma_bf16(acc[mt][nt], ah[mt], bh0, bh1);
                    }
                }
            }
        }
        __syncthreads();
    }

#pragma unroll
    for (int mt = 0; mt < 4; mt++) {
        int gr = row0 + warpm * 64 + mt * 16 + gid;
#pragma unroll
        for (int nt = 0; nt < 4; nt++) {
            int gc = col0 + warpn * 32 + nt * 8 + 2 * tig;
            float b0 = 0.f, b1 = 0.f;
            if (bias) { b0 = bias[gc]; b1 = bias[gc + 1]; }
            float2 c01 = {acc[mt][nt][0] + b0, acc[mt][nt][1] + b1};
            float2 c23 = {acc[mt][nt][2] + b0, acc[mt][nt][3] + b1};
            *(float2*)(C + (size_t)gr * N + gc) = c01;
            *(float2*)(C + (size_t)(gr + 8) * N + gc) = c23;
        }
    }
}

// ----------------------------------------------------------------------------
// RMSNorm (over D=64) + RoPE; split qkv into q/k/v in [B,H,L,D].
// K and V pre-rounded to tf32 (bit-identical to converting at staging time).
// ----------------------------------------------------------------------------
__global__ __launch_bounds__(256) void rmsrope_kernel(
    const float* __restrict__ qkv, const float* __restrict__ pe,
    const float* __restrict__ qscale, const float* __restrict__ kscale,
    float* __restrict__ q, float* __restrict__ k, float* __restrict__ v)
{
    const int warp = (blockIdx.x * blockDim.x + threadIdx.x) >> 5;
    const int lane = threadIdx.x & 31;
    const int b = warp >> 15;
    const int rem = warp & 32767;
    const int h = rem >> 11;
    const int l = rem & 2047;

    const float* base = qkv + ((size_t)(b * L_ + l)) * (3 * DIM_) + h * D_;
    float2 q2 = *(const float2*)(base + lane * 2);
    float2 k2 = *(const float2*)(base + DIM_ + lane * 2);
    float2 v2 = *(const float2*)(base + 2 * DIM_ + lane * 2);

    float sq = q2.x * q2.x + q2.y * q2.y;
    float sk = k2.x * k2.x + k2.y * k2.y;
#pragma unroll
    for (int o = 16; o > 0; o >>= 1) {
        sq += __shfl_xor_sync(0xffffffffu, sq, o);
        sk += __shfl_xor_sync(0xffffffffu, sk, o);
    }
    const float qinv = rsqrtf(sq * (1.f / 64.f) + 1e-6f);
    const float kinv = rsqrtf(sk * (1.f / 64.f) + 1e-6f);

    float2 qsc = *(const float2*)(qscale + lane * 2);
    float2 ksc = *(const float2*)(kscale + lane * 2);
    float t0 = q2.x * qinv * qsc.x;
    float t1 = q2.y * qinv * qsc.y;
    float u0 = k2.x * kinv * ksc.x;
    float u1 = k2.y * kinv * ksc.y;

    float4 p = *(const float4*)(pe + (((size_t)(b * L_ + l)) * 32 + lane) * 4);
    float2 qo, ko;
    qo.x = p.x * t0 + p.y * t1;
    qo.y = p.z * t0 + p.w * t1;
    ko.x = p.x * u0 + p.y * u1;
    ko.y = p.z * u0 + p.w * u1;

    const size_t orow = ((size_t)((b * H_ + h) * L_ + l)) * D_;
    *(float2*)(q + orow + lane * 2) = qo;
    uint2 kt = {f2tf32(ko.x), f2tf32(ko.y)};
    uint2 vt = {f2tf32(v2.x), f2tf32(v2.y)};
    *(uint2*)(k + orow + lane * 2) = kt;
    *(uint2*)(v + orow + lane * 2) = vt;
}

// ----------------------------------------------------------------------------
// Flash attention (tf32 mma), 4 warps / 64 queries per block, double-buffered
// cp.async staging. P-staging reuses the SPENT K buffer (K[t&1] is dead after
// the S-phase), cutting smem 87->68KB so 3 CTAs/SM fit (launch_bounds(128,3)).
// One extra __syncthreads between S-phase and P-store guards the reuse.
// ----------------------------------------------------------------------------
#define PAD 68
#define TILEF (64 * PAD)
#define ATTN_SMEM_FLOATS (4 * TILEF)
#define ATTN_SMEM_BYTES  (ATTN_SMEM_FLOATS * 4)   // 69632

__global__ __launch_bounds__(128, 3) void attn_mma(
    const float* __restrict__ q, const float* __restrict__ k,
    const float* __restrict__ v,
    __nv_bfloat16* __restrict__ oh, __nv_bfloat16* __restrict__ ol)
{
    extern __shared__ float sm[];
    const uint32_t smem_u32 = (uint32_t)__cvta_generic_to_shared(sm);

    const int tid  = threadIdx.x;
    const int lane = tid & 31;
    const int warp = tid >> 5;
    const int gid  = lane >> 2;
    const int tig  = lane & 3;
    const int bh = blockIdx.y;
    const int q0 = blockIdx.x * 64;
    const size_t bhoff = (size_t)bh * L_ * D_;
    const float* Q = q + bhoff;
    const float* K = k + bhoff;
    const float* V = v + bhoff;

    const float QSCALE = 0.125f * 1.4426950408889634f;

    const int sr  = tid >> 4;
    const int sc4 = tid & 15;
    const uint32_t sdst = (uint32_t)((sr * PAD + sc4 * 4) * 4);
    const float* ksrc = K + (size_t)sr * D_ + sc4 * 4;
    const float* vsrc = V + (size_t)sr * D_ + sc4 * 4;

    const int r0 = q0 + warp * 16 + gid;
    uint32_t qf[8][4];
#pragma unroll
    for (int kk = 0; kk < 8; kk++) {
        qf[kk][0] = f2tf32(Q[(size_t)r0 * D_ + kk * 8 + tig] * QSCALE);
        qf[kk][1] = f2tf32(Q[(size_t)(r0 + 8) * D_ + kk * 8 + tig] * QSCALE);
        qf[kk][2] = f2tf32(Q[(size_t)r0 * D_ + kk * 8 + tig + 4] * QSCALE);
        qf[kk][3] = f2tf32(Q[(size_t)(r0 + 8) * D_ + kk * 8 + tig + 4] * QSCALE);
    }

    float of[8][4];
#pragma unroll
    for (int nt = 0; nt < 8; nt++)
#pragma unroll
        for (int j = 0; j < 4; j++) of[nt][j] = 0.f;

    float m0 = -INFINITY, m1 = -INFINITY;
    float l0 = 0.f, l1 = 0.f;

    const int ntiles = L_ / 64;

    // prologue: stage tile 0 into buffer 0 (K at buf, V at 2*TILEF + buf)
#pragma unroll
    for (int it = 0; it < 8; it++) {
        cpa16(smem_u32 + sdst + (uint32_t)(it * 8 * PAD * 4),
              ksrc + (size_t)(it * 8) * D_);
        cpa16(smem_u32 + (uint32_t)(2 * TILEF * 4) + sdst + (uint32_t)(it * 8 * PAD * 4),
              vsrc + (size_t)(it * 8) * D_);
    }
    CP_COMMIT();

    for (int t = 0; t < ntiles; t++) {
        if (t + 1 < ntiles) {
            const uint32_t bb = (uint32_t)(((t + 1) & 1) * TILEF * 4);
            const float* kn = ksrc + (size_t)(t + 1) * 64 * D_;
            const float* vn = vsrc + (size_t)(t + 1) * 64 * D_;
#pragma unroll
            for (int it = 0; it < 8; it++) {
                cpa16(smem_u32 + bb + sdst + (uint32_t)(it * 8 * PAD * 4),
                      kn + (size_t)(it * 8) * D_);
                cpa16(smem_u32 + (uint32_t)(2 * TILEF * 4) + bb + sdst + (uint32_t)(it * 8 * PAD * 4),
                      vn + (size_t)(it * 8) * D_);
            }
            CP_COMMIT();
            CP_WAIT1();
        } else {
            CP_WAIT0();
        }
        __syncthreads();

        const uint32_t* sKu = (const uint32_t*)(sm + (t & 1) * TILEF);
        const uint32_t* sVu = (const uint32_t*)(sm + 2 * TILEF + (t & 1) * TILEF);
        // P staging region: this warp's quarter of the (now spent) K buffer
        uint32_t* sPw = (uint32_t*)(sm + (t & 1) * TILEF) + warp * 16 * PAD;

        // ---- S = Q K^T ----
        float sf[8][4];
#pragma unroll
        for (int nt = 0; nt < 8; nt++)
#pragma unroll
            for (int j = 0; j < 4; j++) sf[nt][j] = 0.f;

#pragma unroll
        for (int kk = 0; kk < 8; kk++) {
#pragma unroll
            for (int nt = 0; nt < 8; nt++) {
                uint32_t b0 = sKu[(nt * 8 + gid) * PAD + kk * 8 + tig];
                uint32_t b1 = sKu[(nt * 8 + gid) * PAD + kk * 8 + tig + 4];
                mma_tf32(sf[nt], qf[kk], b0, b1);
            }
        }

        // ---- max reduction (registers only, pre-barrier) ----
        float mn0 = m0, mn1 = m1;
#pragma unroll
        for (int nt = 0; nt < 8; nt++) {
            mn0 = fmaxf(mn0, fmaxf(sf[nt][0], sf[nt][1]));
            mn1 = fmaxf(mn1, fmaxf(sf[nt][2], sf[nt][3]));
        }
        mn0 = fmaxf(mn0, __shfl_xor_sync(0xffffffffu, mn0, 1));
        mn0 = fmaxf(mn0, __shfl_xor_sync(0xffffffffu, mn0, 2));
        mn1 = fmaxf(mn1, __shfl_xor_sync(0xffffffffu, mn1, 1));
        mn1 = fmaxf(mn1, __shfl_xor_sync(0xffffffffu, mn1, 2));
        float a0 = exp2f(m0 - mn0);
        float a1 = exp2f(m1 - mn1);
        m0 = mn0; m1 = mn1;
        l0 *= a0; l1 *= a1;

        // all warps must be done reading K before P overwrites it
        __syncthreads();

        // ---- exp + P store (into spent K buffer) ----
#pragma unroll
        for (int nt = 0; nt < 8; nt++) {
            float p00 = exp2f(sf[nt][0] - m0);
            float p01 = exp2f(sf[nt][1] - m0);
            float p10 = exp2f(sf[nt][2] - m1);
            float p11 = exp2f(sf[nt][3] - m1);
            l0 += p00 + p01;
            l1 += p10 + p11;
            uint2 u0 = {f2tf32(p00), f2tf32(p01)};
            uint2 u1 = {f2tf32(p10), f2tf32(p11)};
            *(uint2*)(&sPw[gid * PAD + nt * 8 + 2 * tig]) = u0;
            *(uint2*)(&sPw[(gid + 8) * PAD + nt * 8 + 2 * tig]) = u1;
            of[nt][0] *= a0; of[nt][1] *= a0;
            of[nt][2] *= a1; of[nt][3] *= a1;
        }
        __syncwarp();

        // ---- O += P @ V ----
#pragma unroll
        for (int kk = 0; kk < 8; kk++) {
            uint32_t af[4];
            af[0] = sPw[gid * PAD + kk * 8 + tig];
            af[1] = sPw[(gid + 8) * PAD + kk * 8 + tig];
            af[2] = sPw[gid * PAD + kk * 8 + tig + 4];
            af[3] = sPw[(gid + 8) * PAD + kk * 8 + tig + 4];
#pragma unroll
            for (int nt = 0; nt < 8; nt++) {
                uint32_t b0 = sVu[(kk * 8 + tig) * PAD + nt * 8 + gid];
                uint32_t b1 = sVu[(kk * 8 + tig + 4) * PAD + nt * 8 + gid];
                mma_tf32(of[nt], af, b0, b1);
            }
        }
        __syncthreads();
    }

    // ---- epilogue: normalize + fused bf16 hi/lo split, [B,L,H,D] ----
    l0 += __shfl_xor_sync(0xffffffffu, l0, 1);
    l0 += __shfl_xor_sync(0xffffffffu, l0, 2);
    l1 += __shfl_xor_sync(0xffffffffu, l1, 1);
    l1 += __shfl_xor_sync(0xffffffffu, l1, 2);
    const float inv0 = 1.f / l0;
    const float inv1 = 1.f / l1;

    const int b = bh >> 4;
    const int h = bh & 15;
    const size_t row0 = (((size_t)(b * L_ + r0)) * H_ + h) * D_;
    const size_t row1 = (((size_t)(b * L_ + r0 + 8)) * H_ + h) * D_;
#pragma unroll
    for (int nt = 0; nt < 8; nt++) {
        float v00 = of[nt][0] * inv0, v01 = of[nt][1] * inv0;
        float v10 = of[nt][2] * inv1, v11 = of[nt][3] * inv1;
        __nv_bfloat16 h0, l0b, h1, l1b, h2, l2b, h3, l3b;
        bfsplit(v00, h0, l0b); bfsplit(v01, h1, l1b);
        bfsplit(v10, h2, l2b); bfsplit(v11, h3, l3b);
        uint32_t ph0 = (uint32_t)__bfloat16_as_ushort(h0) | ((uint32_t)__bfloat16_as_ushort(h1) << 16);
        uint32_t pl0 = (uint32_t)__bfloat16_as_ushort(l0b) | ((uint32_t)__bfloat16_as_ushort(l1b) << 16);
        uint32_t ph1 = (uint32_t)__bfloat16_as_ushort(h2) | ((uint32_t)__bfloat16_as_ushort(h3) << 16);
        uint32_t pl1 = (uint32_t)__bfloat16_as_ushort(l2b) | ((uint32_t)__bfloat16_as_ushort(l3b) << 16);
        *(uint32_t*)(oh + row0 + nt * 8 + 2 * tig) = ph0;
        *(uint32_t*)(ol + row0 + nt * 8 + 2 * tig) = pl0;
        *(uint32_t*)(oh + row1 + nt * 8 + 2 * tig) = ph1;
        *(uint32_t*)(ol + row1 + nt * 8 + 2 * tig) = pl1;
    }
}

// ----------------------------------------------------------------------------
// Launch
// ----------------------------------------------------------------------------
extern "C" void kernel_launch(void* const* d_in, const int* in_sizes, int n_in,
                              void* d_out, int out_size)
{
    const float* x      = (const float*)d_in[0];
    const float* pe     = (const float*)d_in[1];
    const float* w_qkv  = (const float*)d_in[2];
    const float* qscale = (const float*)d_in[3];
    const float* kscale = (const float*)d_in[4];
    const float* w_proj = (const float*)d_in[5];
    const float* b_proj = (const float*)d_in[6];
    float* out = (float*)d_out;

    float *p_qkv, *p_q, *p_k, *p_v;
    cudaGetSymbolAddress((void**)&p_qkv, g_qkv);
    cudaGetSymbolAddress((void**)&p_q, g_q);
    cudaGetSymbolAddress((void**)&p_k, g_k);
    cudaGetSymbolAddress((void**)&p_v, g_v);

    __nv_bfloat16 *p_xh, *p_xl, *p_wqh, *p_wql, *p_wph, *p_wpl, *p_oh, *p_ol;
    cudaGetSymbolAddress((void**)&p_xh, g_xh);
    cudaGetSymbolAddress((void**)&p_xl, g_xl);
    cudaGetSymbolAddress((void**)&p_wqh, g_wqh);
    cudaGetSymbolAddress((void**)&p_wql, g_wql);
    cudaGetSymbolAddress((void**)&p_wph, g_wph);
    cudaGetSymbolAddress((void**)&p_wpl, g_wpl);
    cudaGetSymbolAddress((void**)&p_oh, g_oh);
    cudaGetSymbolAddress((void**)&p_ol, g_ol);

    cudaFuncSetAttribute(attn_mma, cudaFuncAttributeMaxDynamicSharedMemorySize,
                         ATTN_SMEM_BYTES);
    cudaFuncSetAttribute(gemm_bf16s, cudaFuncAttributeMaxDynamicSharedMemorySize,
                         GEMM_SMEM_BYTES);

    // 0a. split x -> bf16 hi/lo
    split_kernel<<<BL_ * DIM_ / 1024, 256>>>(x, p_xh, p_xl, BL_ * DIM_);
    // 0b. transpose+split weights
    {
        dim3 gq(3 * DIM_ / 32, DIM_ / 32);
        tsplit_kernel<<<gq, 256>>>(w_qkv, p_wqh, p_wql, DIM_, 3 * DIM_);
        dim3 gp(DIM_ / 32, DIM_ / 32);
        tsplit_kernel<<<gp, 256>>>(w_proj, p_wph, p_wpl, DIM_, DIM_);
    }
    // 1. QKV GEMM (bf16 3-term, ldmatrix): [4096,1024] @ [1024,3072]
    {
        dim3 grid(3 * DIM_ / 128, BL_ / 128);
        gemm_bf16s<<<grid, 256, GEMM_SMEM_BYTES>>>(p_xh, p_xl, p_wqh, p_wql,
                                                   nullptr, p_qkv,
                                                   BL_, 3 * DIM_, DIM_);
    }
    // 2. RMSNorm + RoPE + split (K/V pre-rounded to tf32)
    {
        int warps = B_ * H_ * L_;
        rmsrope_kernel<<<warps * 32 / 256, 256>>>(p_qkv, pe, qscale, kscale,
                                                  p_q, p_k, p_v);
    }
    // 3. Attention (tf32 mma, K-buffer-reuse P staging, 3 CTAs/SM)
    {
        dim3 grid(L_ / 64, BH_);
        attn_mma<<<grid, 128, ATTN_SMEM_BYTES>>>(p_q, p_k, p_v, p_oh, p_ol);
    }
    // 4. Output projection (bf16 3-term) + bias
    {
        dim3 grid(DIM_ / 128, BL_ / 128);
        gemm_bf16s<<<grid, 256, GEMM_SMEM_BYTES>>>(p_oh, p_ol, p_wph, p_wpl,
                                                   b_proj, out,
                                                   BL_, DIM_, DIM_);
    }
}